// round 5
// baseline (speedup 1.0000x reference)
#include <cuda_runtime.h>

#define NGAUSS 2048
#define NCH    32
#define IMH    80
#define IMW    144
#define NVIEW  2
#define NEARP  0.2f
#define DILATE 0.3f
#define ALPHA_MIN (1.0f/255.0f)
#define T_EPS  1e-4f
#define BATCH  256   // gaussians culled per warp round (8 chunks of 32)

// unsorted per-gaussian attrs: [0]={px,py,ca,cb} [1]={cc,op,tz,idx} ; cull={px,py,rx,ry}
__device__ float4 g_attr  [NVIEW][NGAUSS][2];
__device__ float4 g_cullu [NVIEW][NGAUSS];
// depth-sorted copies
__device__ float4 g_sorted[NVIEW][NGAUSS][2];
__device__ float4 g_cull  [NVIEW][NGAUSS];

// ---------------------------------------------------------------------------
// Phase 1+2: projection + conic + bbox radii, then stable bitonic depth sort.
// One CTA per view, 1024 threads. Bitonic steps with j<=32 are warp-local
// (each warp owns a disjoint 64-element block) -> __syncwarp only.
// ---------------------------------------------------------------------------
__global__ void prep_sort(const float* __restrict__ means,
                          const float* __restrict__ opac,
                          const float* __restrict__ scales,
                          const float* __restrict__ rots,
                          const float* __restrict__ cam2img,
                          const float* __restrict__ cam2ego)
{
    const int v   = blockIdx.x;
    const int tid = threadIdx.x;
    __shared__ unsigned long long keys[NGAUSS];

    const float* Km = cam2img + v * 9;
    const float* E  = cam2ego + v * 16;
    const float fx = Km[0], fy = Km[4], cx = Km[2], cy = Km[5];

    const float R00 = E[0], R01 = E[4], R02 = E[8];
    const float R10 = E[1], R11 = E[5], R12 = E[9];
    const float R20 = E[2], R21 = E[6], R22 = E[10];
    const float ex = E[3], ey = E[7], ez = E[11];
    const float Tx = -(R00*ex + R01*ey + R02*ez);
    const float Ty = -(R10*ex + R11*ey + R12*ez);
    const float Tz = -(R20*ex + R21*ey + R22*ez);
    const float tanfovx = (float)IMW * 0.5f / fx;
    const float tanfovy = (float)IMH * 0.5f / fy;

    for (int n = tid; n < NGAUSS; n += blockDim.x) {
        float qw = rots[n*4+0], qx = rots[n*4+1], qy = rots[n*4+2], qz = rots[n*4+3];
        float inv = rsqrtf(qw*qw + qx*qx + qy*qy + qz*qz);
        qw *= inv; qx *= inv; qy *= inv; qz *= inv;
        float r00 = 1.f - 2.f*(qy*qy + qz*qz), r01 = 2.f*(qx*qy - qw*qz), r02 = 2.f*(qx*qz + qw*qy);
        float r10 = 2.f*(qx*qy + qw*qz), r11 = 1.f - 2.f*(qx*qx + qz*qz), r12 = 2.f*(qy*qz - qw*qx);
        float r20 = 2.f*(qx*qz - qw*qy), r21 = 2.f*(qy*qz + qw*qx), r22 = 1.f - 2.f*(qx*qx + qy*qy);

        float sx = scales[n*3+0], sy = scales[n*3+1], sz = scales[n*3+2];
        float m00 = r00*sx, m01 = r01*sy, m02 = r02*sz;
        float m10 = r10*sx, m11 = r11*sy, m12 = r12*sz;
        float m20 = r20*sx, m21 = r21*sy, m22 = r22*sz;

        float S00 = m00*m00 + m01*m01 + m02*m02;
        float S01 = m00*m10 + m01*m11 + m02*m12;
        float S02 = m00*m20 + m01*m21 + m02*m22;
        float S11 = m10*m10 + m11*m11 + m12*m12;
        float S12 = m10*m20 + m11*m21 + m12*m22;
        float S22 = m20*m20 + m21*m21 + m22*m22;

        float mx = means[n*3+0], my = means[n*3+1], mz = means[n*3+2];
        float tx = R00*mx + R01*my + R02*mz + Tx;
        float ty = R10*mx + R11*my + R12*mz + Ty;
        float tz = R20*mx + R21*my + R22*mz + Tz;

        bool  valid = tz > NEARP;
        float tzs   = valid ? tz : 1.0f;
        float txtz  = fminf(fmaxf(tx/tzs, -1.3f*tanfovx), 1.3f*tanfovx);
        float tytz  = fminf(fmaxf(ty/tzs, -1.3f*tanfovy), 1.3f*tanfovy);

        float A00 = R00*S00 + R01*S01 + R02*S02;
        float A01 = R00*S01 + R01*S11 + R02*S12;
        float A02 = R00*S02 + R01*S12 + R02*S22;
        float A10 = R10*S00 + R11*S01 + R12*S02;
        float A11 = R10*S01 + R11*S11 + R12*S12;
        float A12 = R10*S02 + R11*S12 + R12*S22;
        float A20 = R20*S00 + R21*S01 + R22*S02;
        float A21 = R20*S01 + R21*S11 + R22*S12;
        float A22 = R20*S02 + R21*S12 + R22*S22;
        float C00 = A00*R00 + A01*R01 + A02*R02;
        float C01 = A00*R10 + A01*R11 + A02*R12;
        float C02 = A00*R20 + A01*R21 + A02*R22;
        float C11 = A10*R10 + A11*R11 + A12*R12;
        float C12 = A10*R20 + A11*R21 + A12*R22;
        float C22 = A20*R20 + A21*R21 + A22*R22;

        float j00 = fx / tzs, j02 = -fx * txtz / tzs;
        float j11 = fy / tzs, j12 = -fy * tytz / tzs;
        float u0 = j00*C00 + j02*C02;
        float u1 = j00*C01 + j02*C12;
        float u2 = j00*C02 + j02*C22;
        float w1 = j11*C11 + j12*C12;
        float w2 = j11*C12 + j12*C22;
        float cov00 = u0*j00 + u2*j02;
        float cov01 = u1*j11 + u2*j12;
        float cov11 = w1*j11 + w2*j12;

        float a = cov00 + DILATE, b = cov01, c = cov11 + DILATE;
        float det = a*c - b*b;
        if (det == 0.f) det = 1.f;
        float ca = c / det, cb = -b / det, cc = a / det;

        float px = fx * tx / tzs + ((float)IMW - cx) - 0.5f;
        float py = fy * ty / tzs + ((float)IMH - cy) - 0.5f;
        float op = valid ? opac[n] : 0.f;

        // bbox radii of the alpha >= 1/255 level set: Q <= t, t = ln(255*op)
        // op<=1/255 or op==0 -> t<=0 or NaN -> rx/ry NaN -> all bbox compares false -> culled
        float t  = __logf(255.f * op);
        float rx = sqrtf(2.f * t * a) * 1.0001f + 1e-3f;
        float ry = sqrtf(2.f * t * c) * 1.0001f + 1e-3f;

        g_attr [v][n][0] = make_float4(px, py, ca, cb);
        g_attr [v][n][1] = make_float4(cc, op, tz, __int_as_float(n));
        g_cullu[v][n]    = make_float4(px, py, rx, ry);

        float keyf = valid ? tz : __int_as_float(0x7F800000);  // +inf
        keys[n] = (((unsigned long long)__float_as_uint(keyf)) << 32) | (unsigned)n;
    }
    __syncthreads();

    // bitonic sort, ascending; idx in low bits => stable (matches jnp.argsort).
    // warp w exclusively owns keys[64w..64w+64) for all steps with j <= 32.
    unsigned prevj = 1;
    for (unsigned k = 2; k <= NGAUSS; k <<= 1) {
        for (unsigned j = k >> 1; j > 0; j >>= 1) {
            if (j >= 64 || prevj >= 64) __syncthreads(); else __syncwarp();
            unsigned t = tid;
            unsigned i   = ((t & ~(j - 1u)) << 1) | (t & (j - 1u));
            unsigned ixj = i | j;
            unsigned long long a0 = keys[i], b0 = keys[ixj];
            bool up = ((i & k) == 0);
            if ((a0 > b0) == up) { keys[i] = b0; keys[ixj] = a0; }
            prevj = j;
        }
    }
    __syncthreads();

    for (int i = tid; i < NGAUSS; i += blockDim.x) {
        unsigned idx = (unsigned)(keys[i] & 0xFFFFFFFFu);
        g_sorted[v][i][0] = g_attr [v][idx][0];
        g_sorted[v][i][1] = g_attr [v][idx][1];
        g_cull  [v][i]    = g_cullu[v][idx];
    }
}

// ---------------------------------------------------------------------------
// Phase 3: single-warp tiles (8x4 pixels, 32 threads). Depth-ordered tile
// culling via ballot/popc only — no block barriers anywhere.
// ---------------------------------------------------------------------------
__global__ void __launch_bounds__(32) render(const float* __restrict__ colors,
                                             float* __restrict__ out)
{
    const int v    = blockIdx.z;
    const int lane = threadIdx.x;
    const int ix   = blockIdx.x * 8 + (lane & 7);
    const int iy   = blockIdx.y * 4 + (lane >> 3);
    const float X = (float)ix, Y = (float)iy;

    const float xmin = (float)(blockIdx.x * 8);
    const float xmax = xmin + 7.0f;
    const float ymin = (float)(blockIdx.y * 4);
    const float ymax = ymin + 3.0f;

    float acc[NCH];
#pragma unroll
    for (int c = 0; c < NCH; c++) acc[c] = 0.f;
    float dacc = 0.f;
    float T = 1.f;
    bool done = false;

    __shared__ float4 s0[BATCH], s1[BATCH];
    const unsigned lmask = (1u << lane) - 1u;

    for (int base = 0; base < NGAUSS; base += BATCH) {
        // 8 chunks of 32: issue all cull loads up front (MLP=8)
        float4 cd[8];
#pragma unroll
        for (int c = 0; c < 8; c++) cd[c] = g_cull[v][base + c * 32 + lane];

        bool hit[8];
        unsigned bal[8];
#pragma unroll
        for (int c = 0; c < 8; c++) {
            // NaN-safe: any NaN -> false -> culled
            hit[c] = (cd[c].x - cd[c].z <= xmax) && (cd[c].x + cd[c].z >= xmin) &&
                     (cd[c].y - cd[c].w <= ymax) && (cd[c].y + cd[c].w >= ymin);
            bal[c] = __ballot_sync(0xffffffffu, hit[c]);
        }

        int offc[8], pre = 0;
#pragma unroll
        for (int c = 0; c < 8; c++) { offc[c] = pre; pre += __popc(bal[c]); }
        const int total = pre;

        __syncwarp();   // prior round's s0/s1 reads complete before overwrite
#pragma unroll
        for (int c = 0; c < 8; c++) {
            if (hit[c]) {
                int off = offc[c] + __popc(bal[c] & lmask);
                int g = base + c * 32 + lane;
                s0[off] = g_sorted[v][g][0];
                s1[off] = g_sorted[v][g][1];
            }
        }
        __syncwarp();

        if (!done) {
            for (int j = 0; j < total; j++) {
                float4 A = s0[j];
                float4 B = s1[j];
                float dx = X - A.x, dy = Y - A.y;
                float power = -0.5f * (A.z * dx * dx + B.x * dy * dy) - A.w * dx * dy;
                float al = fminf(0.99f, B.y * __expf(power));
                if (power > 0.f || !(al >= ALPHA_MIN)) continue;
                float Tn = T * (1.f - al);
                if (Tn >= T_EPS) {
                    float w = al * T;
                    const float4* crow =
                        (const float4*)(colors + (size_t)((unsigned)__float_as_int(B.w)) * NCH);
#pragma unroll
                    for (int c4 = 0; c4 < 8; c4++) {
                        float4 cv = crow[c4];
                        acc[c4*4+0] += w * cv.x;
                        acc[c4*4+1] += w * cv.y;
                        acc[c4*4+2] += w * cv.z;
                        acc[c4*4+3] += w * cv.w;
                    }
                    dacc += w * B.z;
                }
                T = Tn;
                if (T < T_EPS) { done = true; break; }   // all later weights are 0
            }
        }
        if (__all_sync(0xffffffffu, done)) break;
    }

#pragma unroll
    for (int c = 0; c < NCH; c++)
        out[((size_t)(v * NCH + c) * IMH + iy) * IMW + ix] = acc[c];
    out[(size_t)NVIEW * NCH * IMH * IMW + (size_t)(v * IMH + iy) * IMW + ix] = dacc;
}

// ---------------------------------------------------------------------------
extern "C" void kernel_launch(void* const* d_in, const int* in_sizes, int n_in,
                              void* d_out, int out_size)
{
    const float* means   = (const float*)d_in[0];
    const float* colors  = (const float*)d_in[1];
    const float* opac    = (const float*)d_in[2];
    const float* scales  = (const float*)d_in[3];
    const float* rots    = (const float*)d_in[4];
    const float* cam2img = (const float*)d_in[5];
    const float* cam2ego = (const float*)d_in[6];
    float* out = (float*)d_out;

    prep_sort<<<NVIEW, 1024>>>(means, opac, scales, rots, cam2img, cam2ego);
    render<<<dim3(IMW/8, IMH/4, NVIEW), dim3(32, 1)>>>(colors, out);
}

// round 6
// speedup vs baseline: 1.1562x; 1.1562x over previous
#include <cuda_runtime.h>

#define NGAUSS 2048
#define NCH    32
#define IMH    80
#define IMW    144
#define NVIEW  2
#define NEARP  0.2f
#define DILATE 0.3f
#define ALPHA_MIN (1.0f/255.0f)
#define T_EPS  1e-4f
#define BATCH  256   // gaussians culled per round (4 chunks of 64)

// unsorted per-gaussian attrs: [0]={px,py,ca,cb} [1]={cc,op,tz,idx} ; cull={px,py,rx,ry}
__device__ float4 g_attr  [NVIEW][NGAUSS][2];
__device__ float4 g_cullu [NVIEW][NGAUSS];
__device__ unsigned long long g_keys[NVIEW][NGAUSS];
// depth-sorted copies
__device__ float4 g_sorted[NVIEW][NGAUSS][2];
__device__ float4 g_cull  [NVIEW][NGAUSS];

// ---------------------------------------------------------------------------
// Phase 1: projection + conic + bbox radii. Wide grid: 16 CTAs x 256 threads.
// ---------------------------------------------------------------------------
__global__ void project(const float* __restrict__ means,
                        const float* __restrict__ opac,
                        const float* __restrict__ scales,
                        const float* __restrict__ rots,
                        const float* __restrict__ cam2img,
                        const float* __restrict__ cam2ego)
{
    const int v = blockIdx.x;
    const int n = blockIdx.y * 256 + threadIdx.x;
    if (n >= NGAUSS) return;

    const float* Km = cam2img + v * 9;
    const float* E  = cam2ego + v * 16;
    const float fx = Km[0], fy = Km[4], cx = Km[2], cy = Km[5];

    const float R00 = E[0], R01 = E[4], R02 = E[8];
    const float R10 = E[1], R11 = E[5], R12 = E[9];
    const float R20 = E[2], R21 = E[6], R22 = E[10];
    const float ex = E[3], ey = E[7], ez = E[11];
    const float Tx = -(R00*ex + R01*ey + R02*ez);
    const float Ty = -(R10*ex + R11*ey + R12*ez);
    const float Tz = -(R20*ex + R21*ey + R22*ez);
    const float tanfovx = (float)IMW * 0.5f / fx;
    const float tanfovy = (float)IMH * 0.5f / fy;

    float qw = rots[n*4+0], qx = rots[n*4+1], qy = rots[n*4+2], qz = rots[n*4+3];
    float inv = rsqrtf(qw*qw + qx*qx + qy*qy + qz*qz);
    qw *= inv; qx *= inv; qy *= inv; qz *= inv;
    float r00 = 1.f - 2.f*(qy*qy + qz*qz), r01 = 2.f*(qx*qy - qw*qz), r02 = 2.f*(qx*qz + qw*qy);
    float r10 = 2.f*(qx*qy + qw*qz), r11 = 1.f - 2.f*(qx*qx + qz*qz), r12 = 2.f*(qy*qz - qw*qx);
    float r20 = 2.f*(qx*qz - qw*qy), r21 = 2.f*(qy*qz + qw*qx), r22 = 1.f - 2.f*(qx*qx + qy*qy);

    float sx = scales[n*3+0], sy = scales[n*3+1], sz = scales[n*3+2];
    float m00 = r00*sx, m01 = r01*sy, m02 = r02*sz;
    float m10 = r10*sx, m11 = r11*sy, m12 = r12*sz;
    float m20 = r20*sx, m21 = r21*sy, m22 = r22*sz;

    float S00 = m00*m00 + m01*m01 + m02*m02;
    float S01 = m00*m10 + m01*m11 + m02*m12;
    float S02 = m00*m20 + m01*m21 + m02*m22;
    float S11 = m10*m10 + m11*m11 + m12*m12;
    float S12 = m10*m20 + m11*m21 + m12*m22;
    float S22 = m20*m20 + m21*m21 + m22*m22;

    float mx = means[n*3+0], my = means[n*3+1], mz = means[n*3+2];
    float tx = R00*mx + R01*my + R02*mz + Tx;
    float ty = R10*mx + R11*my + R12*mz + Ty;
    float tz = R20*mx + R21*my + R22*mz + Tz;

    bool  valid = tz > NEARP;
    float tzs   = valid ? tz : 1.0f;
    float txtz  = fminf(fmaxf(tx/tzs, -1.3f*tanfovx), 1.3f*tanfovx);
    float tytz  = fminf(fmaxf(ty/tzs, -1.3f*tanfovy), 1.3f*tanfovy);

    float A00 = R00*S00 + R01*S01 + R02*S02;
    float A01 = R00*S01 + R01*S11 + R02*S12;
    float A02 = R00*S02 + R01*S12 + R02*S22;
    float A10 = R10*S00 + R11*S01 + R12*S02;
    float A11 = R10*S01 + R11*S11 + R12*S12;
    float A12 = R10*S02 + R11*S12 + R12*S22;
    float A20 = R20*S00 + R21*S01 + R22*S02;
    float A21 = R20*S01 + R21*S11 + R22*S12;
    float A22 = R20*S02 + R21*S12 + R22*S22;
    float C00 = A00*R00 + A01*R01 + A02*R02;
    float C01 = A00*R10 + A01*R11 + A02*R12;
    float C02 = A00*R20 + A01*R21 + A02*R22;
    float C11 = A10*R10 + A11*R11 + A12*R12;
    float C12 = A10*R20 + A11*R21 + A12*R22;
    float C22 = A20*R20 + A21*R21 + A22*R22;

    float j00 = fx / tzs, j02 = -fx * txtz / tzs;
    float j11 = fy / tzs, j12 = -fy * tytz / tzs;
    float u0 = j00*C00 + j02*C02;
    float u1 = j00*C01 + j02*C12;
    float u2 = j00*C02 + j02*C22;
    float w1 = j11*C11 + j12*C12;
    float w2 = j11*C12 + j12*C22;
    float cov00 = u0*j00 + u2*j02;
    float cov01 = u1*j11 + u2*j12;
    float cov11 = w1*j11 + w2*j12;

    float a = cov00 + DILATE, b = cov01, c = cov11 + DILATE;
    float det = a*c - b*b;
    if (det == 0.f) det = 1.f;
    float ca = c / det, cb = -b / det, cc = a / det;

    float px = fx * tx / tzs + ((float)IMW - cx) - 0.5f;
    float py = fy * ty / tzs + ((float)IMH - cy) - 0.5f;
    float op = valid ? opac[n] : 0.f;

    // bbox radii of the alpha >= 1/255 level set: Q <= t, t = ln(255*op)
    // op<=1/255 or op==0 -> t<=0 or NaN -> rx/ry NaN -> all bbox compares false -> culled
    float t  = __logf(255.f * op);
    float rx = sqrtf(2.f * t * a) * 1.0001f + 1e-3f;
    float ry = sqrtf(2.f * t * c) * 1.0001f + 1e-3f;

    g_attr [v][n][0] = make_float4(px, py, ca, cb);
    g_attr [v][n][1] = make_float4(cc, op, tz, __int_as_float(n));
    g_cullu[v][n]    = make_float4(px, py, rx, ry);

    float keyf = valid ? tz : __int_as_float(0x7F800000);  // +inf
    g_keys[v][n] = (((unsigned long long)__float_as_uint(keyf)) << 32) | (unsigned)n;
}

// ---------------------------------------------------------------------------
// Phase 2: stable bitonic depth sort + gather. One CTA per view, 1024 threads.
// Steps with j<=32 are warp-local (each warp owns a disjoint 64-elem block).
// ---------------------------------------------------------------------------
__global__ void sortk()
{
    const int v   = blockIdx.x;
    const int tid = threadIdx.x;
    __shared__ unsigned long long keys[NGAUSS];

    keys[tid]        = g_keys[v][tid];
    keys[tid + 1024] = g_keys[v][tid + 1024];
    __syncthreads();

    unsigned prevj = 1;
    for (unsigned k = 2; k <= NGAUSS; k <<= 1) {
        for (unsigned j = k >> 1; j > 0; j >>= 1) {
            if (j >= 64 || prevj >= 64) __syncthreads(); else __syncwarp();
            unsigned t = tid;
            unsigned i   = ((t & ~(j - 1u)) << 1) | (t & (j - 1u));
            unsigned ixj = i | j;
            unsigned long long a0 = keys[i], b0 = keys[ixj];
            bool up = ((i & k) == 0);
            if ((a0 > b0) == up) { keys[i] = b0; keys[ixj] = a0; }
            prevj = j;
        }
    }
    __syncthreads();

    for (int i = tid; i < NGAUSS; i += 1024) {
        unsigned idx = (unsigned)(keys[i] & 0xFFFFFFFFu);
        g_sorted[v][i][0] = g_attr [v][idx][0];
        g_sorted[v][i][1] = g_attr [v][idx][1];
        g_cull  [v][i]    = g_cullu[v][idx];
    }
}

// ---------------------------------------------------------------------------
// Phase 3: tiled render, 8x8 tiles / 64 threads. Depth-ordered cooperative
// culling; branchless 4-wide unrolled blend loop (grid-limited occupancy, so
// registers are free).
// ---------------------------------------------------------------------------
__global__ void __launch_bounds__(64) render(const float* __restrict__ colors,
                                             float* __restrict__ out)
{
    const int v   = blockIdx.z;
    const int ix  = blockIdx.x * 8 + threadIdx.x;
    const int iy  = blockIdx.y * 8 + threadIdx.y;
    const int tid = threadIdx.y * 8 + threadIdx.x;
    const int wid = tid >> 5, lane = tid & 31;
    const float X = (float)ix, Y = (float)iy;

    const float xmin = (float)(blockIdx.x * 8);
    const float xmax = xmin + 7.0f;
    const float ymin = (float)(blockIdx.y * 8);
    const float ymax = ymin + 7.0f;

    float acc[NCH];
#pragma unroll
    for (int c = 0; c < NCH; c++) acc[c] = 0.f;
    float dacc = 0.f;
    float T = 1.f;

    __shared__ float4 s0[BATCH + 4], s1[BATCH + 4];
    __shared__ unsigned sball[8];   // [chunk*2 + warp], depth order
    const unsigned lmask = (1u << lane) - 1u;

    for (int base = 0; base < NGAUSS; base += BATCH) {
        // 4 chunks of 64: issue all cull loads up front (MLP=4)
        float4 cd[4];
#pragma unroll
        for (int k = 0; k < 4; k++) cd[k] = g_cull[v][base + k * 64 + tid];

        bool hit[4];
        unsigned myb[4];
#pragma unroll
        for (int k = 0; k < 4; k++) {
            // NaN-safe: any NaN -> false -> culled
            hit[k] = (cd[k].x - cd[k].z <= xmax) && (cd[k].x + cd[k].z >= xmin) &&
                     (cd[k].y - cd[k].w <= ymax) && (cd[k].y + cd[k].w >= ymin);
            myb[k] = __ballot_sync(0xffffffffu, hit[k]);
        }
        if (lane == 0) {
#pragma unroll
            for (int k = 0; k < 4; k++) sball[k * 2 + wid] = myb[k];
        }
        __syncthreads();   // ballots visible; also fences prior round's s0/s1 reads

        unsigned bl[8];
        int total = 0;
#pragma unroll
        for (int i = 0; i < 8; i++) { bl[i] = sball[i]; total += __popc(bl[i]); }

#pragma unroll
        for (int k = 0; k < 4; k++) {
            if (hit[k]) {
                int ord = k * 2 + wid;
                int off = 0;
                for (int i = 0; i < ord; i++) off += __popc(bl[i]);
                off += __popc(myb[k] & lmask);
                int g = base + k * 64 + tid;
                s0[off] = g_sorted[v][g][0];
                s1[off] = g_sorted[v][g][1];
            }
        }
        // pad to multiple of 4 with alpha-neutral dummies (op=0 -> al_eff=0)
        int pad = (4 - (total & 3)) & 3;
        if (tid < pad) {
            s0[total + tid] = make_float4(0.f, 0.f, 0.f, 0.f);
            s1[total + tid] = make_float4(0.f, 0.f, 0.f, 0.f);
        }
        int totalp = total + pad;
        __syncthreads();

        for (int j = 0; j < totalp; j += 4) {
            float w4[4], tz4[4];
            int   id4[4];
#pragma unroll
            for (int u = 0; u < 4; u++) {
                float4 A = s0[j + u];
                float4 B = s1[j + u];
                float dx = X - A.x, dy = Y - A.y;
                float power = -0.5f * (A.z * dx * dx + B.x * dy * dy) - A.w * dx * dy;
                float al = fminf(0.99f, B.y * __expf(power));
                // reference: skipped gaussians contribute alpha = 0 (T unchanged)
                bool skip = (power > 0.f) || !(al >= ALPHA_MIN);
                float ale = skip ? 0.f : al;
                float Tn  = T * (1.f - ale);
                w4[u]  = (Tn >= T_EPS) ? ale * T : 0.f;
                tz4[u] = B.z;
                id4[u] = __float_as_int(B.w);
                T = Tn;
            }
#pragma unroll
            for (int u = 0; u < 4; u++) {
                if (w4[u] != 0.f) {
                    float w = w4[u];
                    const float4* crow =
                        (const float4*)(colors + (size_t)((unsigned)id4[u]) * NCH);
#pragma unroll
                    for (int c4 = 0; c4 < 8; c4++) {
                        float4 cv = crow[c4];
                        acc[c4*4+0] += w * cv.x;
                        acc[c4*4+1] += w * cv.y;
                        acc[c4*4+2] += w * cv.z;
                        acc[c4*4+3] += w * cv.w;
                    }
                    dacc += w * tz4[u];
                }
            }
            // warp-local early out (cheap VOTE, no block barrier)
            if (__all_sync(0xffffffffu, T < T_EPS)) break;
        }
        if (__syncthreads_and(T < T_EPS)) break;
    }

#pragma unroll
    for (int c = 0; c < NCH; c++)
        out[((size_t)(v * NCH + c) * IMH + iy) * IMW + ix] = acc[c];
    out[(size_t)NVIEW * NCH * IMH * IMW + (size_t)(v * IMH + iy) * IMW + ix] = dacc;
}

// ---------------------------------------------------------------------------
extern "C" void kernel_launch(void* const* d_in, const int* in_sizes, int n_in,
                              void* d_out, int out_size)
{
    const float* means   = (const float*)d_in[0];
    const float* colors  = (const float*)d_in[1];
    const float* opac    = (const float*)d_in[2];
    const float* scales  = (const float*)d_in[3];
    const float* rots    = (const float*)d_in[4];
    const float* cam2img = (const float*)d_in[5];
    const float* cam2ego = (const float*)d_in[6];
    float* out = (float*)d_out;

    project<<<dim3(NVIEW, NGAUSS / 256), 256>>>(means, opac, scales, rots, cam2img, cam2ego);
    sortk<<<NVIEW, 1024>>>();
    render<<<dim3(IMW/8, IMH/8, NVIEW), dim3(8, 8)>>>(colors, out);
}

// round 7
// speedup vs baseline: 1.4605x; 1.2633x over previous
#include <cuda_runtime.h>

#define NGAUSS 2048
#define NCH    32
#define IMH    80
#define IMW    144
#define NPIX   (IMH*IMW)
#define NVIEW  2
#define NSEG   4
#define SEGLEN (NGAUSS/NSEG)
#define NEARP  0.2f
#define DILATE 0.3f
#define ALPHA_MIN (1.0f/255.0f)
#define T_EPS  1e-4f
#define BATCH  256   // gaussians culled per round (4 chunks of 64)

// unsorted per-gaussian attrs: [0]={px,py,ca,cb} [1]={cc,op,tz,idx} ; cull={px,py,rx,ry}
__device__ float4 g_attr  [NVIEW][NGAUSS][2];
__device__ float4 g_cullu [NVIEW][NGAUSS];
__device__ unsigned long long g_keys[NVIEW][NGAUSS];
// depth-sorted copies
__device__ float4 g_sorted[NVIEW][NGAUSS][2];
__device__ float4 g_cull  [NVIEW][NGAUSS];
// segmented compositing scratch
__device__ float g_T   [NVIEW][NSEG][NPIX];
__device__ float g_part[NVIEW][NSEG][NCH+1][NPIX];

// ---------------------------------------------------------------------------
// Phase 1: projection + conic + bbox radii. Wide grid.
// ---------------------------------------------------------------------------
__global__ void project(const float* __restrict__ means,
                        const float* __restrict__ opac,
                        const float* __restrict__ scales,
                        const float* __restrict__ rots,
                        const float* __restrict__ cam2img,
                        const float* __restrict__ cam2ego)
{
    const int v = blockIdx.x;
    const int n = blockIdx.y * 256 + threadIdx.x;
    if (n >= NGAUSS) return;

    const float* Km = cam2img + v * 9;
    const float* E  = cam2ego + v * 16;
    const float fx = Km[0], fy = Km[4], cx = Km[2], cy = Km[5];

    const float R00 = E[0], R01 = E[4], R02 = E[8];
    const float R10 = E[1], R11 = E[5], R12 = E[9];
    const float R20 = E[2], R21 = E[6], R22 = E[10];
    const float ex = E[3], ey = E[7], ez = E[11];
    const float Tx = -(R00*ex + R01*ey + R02*ez);
    const float Ty = -(R10*ex + R11*ey + R12*ez);
    const float Tz = -(R20*ex + R21*ey + R22*ez);
    const float tanfovx = (float)IMW * 0.5f / fx;
    const float tanfovy = (float)IMH * 0.5f / fy;

    float qw = rots[n*4+0], qx = rots[n*4+1], qy = rots[n*4+2], qz = rots[n*4+3];
    float inv = rsqrtf(qw*qw + qx*qx + qy*qy + qz*qz);
    qw *= inv; qx *= inv; qy *= inv; qz *= inv;
    float r00 = 1.f - 2.f*(qy*qy + qz*qz), r01 = 2.f*(qx*qy - qw*qz), r02 = 2.f*(qx*qz + qw*qy);
    float r10 = 2.f*(qx*qy + qw*qz), r11 = 1.f - 2.f*(qx*qx + qz*qz), r12 = 2.f*(qy*qz - qw*qx);
    float r20 = 2.f*(qx*qz - qw*qy), r21 = 2.f*(qy*qz + qw*qx), r22 = 1.f - 2.f*(qx*qx + qy*qy);

    float sx = scales[n*3+0], sy = scales[n*3+1], sz = scales[n*3+2];
    float m00 = r00*sx, m01 = r01*sy, m02 = r02*sz;
    float m10 = r10*sx, m11 = r11*sy, m12 = r12*sz;
    float m20 = r20*sx, m21 = r21*sy, m22 = r22*sz;

    float S00 = m00*m00 + m01*m01 + m02*m02;
    float S01 = m00*m10 + m01*m11 + m02*m12;
    float S02 = m00*m20 + m01*m21 + m02*m22;
    float S11 = m10*m10 + m11*m11 + m12*m12;
    float S12 = m10*m20 + m11*m21 + m12*m22;
    float S22 = m20*m20 + m21*m21 + m22*m22;

    float mx = means[n*3+0], my = means[n*3+1], mz = means[n*3+2];
    float tx = R00*mx + R01*my + R02*mz + Tx;
    float ty = R10*mx + R11*my + R12*mz + Ty;
    float tz = R20*mx + R21*my + R22*mz + Tz;

    bool  valid = tz > NEARP;
    float tzs   = valid ? tz : 1.0f;
    float txtz  = fminf(fmaxf(tx/tzs, -1.3f*tanfovx), 1.3f*tanfovx);
    float tytz  = fminf(fmaxf(ty/tzs, -1.3f*tanfovy), 1.3f*tanfovy);

    float A00 = R00*S00 + R01*S01 + R02*S02;
    float A01 = R00*S01 + R01*S11 + R02*S12;
    float A02 = R00*S02 + R01*S12 + R02*S22;
    float A10 = R10*S00 + R11*S01 + R12*S02;
    float A11 = R10*S01 + R11*S11 + R12*S12;
    float A12 = R10*S02 + R11*S12 + R12*S22;
    float A20 = R20*S00 + R21*S01 + R22*S02;
    float A21 = R20*S01 + R21*S11 + R22*S12;
    float A22 = R20*S02 + R21*S12 + R22*S22;
    float C00 = A00*R00 + A01*R01 + A02*R02;
    float C01 = A00*R10 + A01*R11 + A02*R12;
    float C02 = A00*R20 + A01*R21 + A02*R22;
    float C11 = A10*R10 + A11*R11 + A12*R12;
    float C12 = A10*R20 + A11*R21 + A12*R22;
    float C22 = A20*R20 + A21*R21 + A22*R22;

    float j00 = fx / tzs, j02 = -fx * txtz / tzs;
    float j11 = fy / tzs, j12 = -fy * tytz / tzs;
    float u0 = j00*C00 + j02*C02;
    float u1 = j00*C01 + j02*C12;
    float u2 = j00*C02 + j02*C22;
    float w1 = j11*C11 + j12*C12;
    float w2 = j11*C12 + j12*C22;
    float cov00 = u0*j00 + u2*j02;
    float cov01 = u1*j11 + u2*j12;
    float cov11 = w1*j11 + w2*j12;

    float a = cov00 + DILATE, b = cov01, c = cov11 + DILATE;
    float det = a*c - b*b;
    if (det == 0.f) det = 1.f;
    float ca = c / det, cb = -b / det, cc = a / det;

    float px = fx * tx / tzs + ((float)IMW - cx) - 0.5f;
    float py = fy * ty / tzs + ((float)IMH - cy) - 0.5f;
    float op = valid ? opac[n] : 0.f;

    // bbox radii of alpha >= 1/255 level set; NaN radii (op<=1/255) -> culled
    float t  = __logf(255.f * op);
    float rx = sqrtf(2.f * t * a) * 1.0001f + 1e-3f;
    float ry = sqrtf(2.f * t * c) * 1.0001f + 1e-3f;

    g_attr [v][n][0] = make_float4(px, py, ca, cb);
    g_attr [v][n][1] = make_float4(cc, op, tz, __int_as_float(n));
    g_cullu[v][n]    = make_float4(px, py, rx, ry);

    float keyf = valid ? tz : __int_as_float(0x7F800000);  // +inf
    g_keys[v][n] = (((unsigned long long)__float_as_uint(keyf)) << 32) | (unsigned)n;
}

// ---------------------------------------------------------------------------
// Phase 2: stable bitonic depth sort + gather. One CTA per view, 1024 threads.
// ---------------------------------------------------------------------------
__global__ void sortk()
{
    const int v   = blockIdx.x;
    const int tid = threadIdx.x;
    __shared__ unsigned long long keys[NGAUSS];

    keys[tid]        = g_keys[v][tid];
    keys[tid + 1024] = g_keys[v][tid + 1024];
    __syncthreads();

    unsigned prevj = 1;
    for (unsigned k = 2; k <= NGAUSS; k <<= 1) {
        for (unsigned j = k >> 1; j > 0; j >>= 1) {
            if (j >= 64 || prevj >= 64) __syncthreads(); else __syncwarp();
            unsigned t = tid;
            unsigned i   = ((t & ~(j - 1u)) << 1) | (t & (j - 1u));
            unsigned ixj = i | j;
            unsigned long long a0 = keys[i], b0 = keys[ixj];
            bool up = ((i & k) == 0);
            if ((a0 > b0) == up) { keys[i] = b0; keys[ixj] = a0; }
            prevj = j;
        }
    }
    __syncthreads();

    for (int i = tid; i < NGAUSS; i += 1024) {
        unsigned idx = (unsigned)(keys[i] & 0xFFFFFFFFu);
        g_sorted[v][i][0] = g_attr [v][idx][0];
        g_sorted[v][i][1] = g_attr [v][idx][1];
        g_cull  [v][i]    = g_cullu[v][idx];
    }
}

// ---------------------------------------------------------------------------
// Cooperative cull+compact of one BATCH into smem (depth order preserved).
// Returns padded count (multiple of 4), dummies have op=0.
// ---------------------------------------------------------------------------
__device__ __forceinline__ int cull_batch(int v, int base, int tid, int wid, int lane,
                                          float xmin, float xmax, float ymin, float ymax,
                                          float4* s0, float4* s1, unsigned* sball)
{
    const unsigned lmask = (1u << lane) - 1u;
    float4 cd[4];
#pragma unroll
    for (int k = 0; k < 4; k++) cd[k] = g_cull[v][base + k * 64 + tid];

    bool hit[4];
    unsigned myb[4];
#pragma unroll
    for (int k = 0; k < 4; k++) {
        hit[k] = (cd[k].x - cd[k].z <= xmax) && (cd[k].x + cd[k].z >= xmin) &&
                 (cd[k].y - cd[k].w <= ymax) && (cd[k].y + cd[k].w >= ymin);
        myb[k] = __ballot_sync(0xffffffffu, hit[k]);
    }
    if (lane == 0) {
#pragma unroll
        for (int k = 0; k < 4; k++) sball[k * 2 + wid] = myb[k];
    }
    __syncthreads();

    unsigned bl[8];
    int total = 0;
#pragma unroll
    for (int i = 0; i < 8; i++) { bl[i] = sball[i]; total += __popc(bl[i]); }

#pragma unroll
    for (int k = 0; k < 4; k++) {
        if (hit[k]) {
            int ord = k * 2 + wid;
            int off = 0;
            for (int i = 0; i < ord; i++) off += __popc(bl[i]);
            off += __popc(myb[k] & lmask);
            int g = base + k * 64 + tid;
            s0[off] = g_sorted[v][g][0];
            s1[off] = g_sorted[v][g][1];
        }
    }
    int pad = (4 - (total & 3)) & 3;
    if (tid < pad) {
        s0[total + tid] = make_float4(0.f, 0.f, 0.f, 0.f);
        s1[total + tid] = make_float4(0.f, 0.f, 0.f, 0.f);
    }
    __syncthreads();
    return total + pad;
}

// ---------------------------------------------------------------------------
// Phase 3a: per-segment transmittance (no color). grid z = v*NSEG+seg.
// ---------------------------------------------------------------------------
__global__ void __launch_bounds__(64) transmit()
{
    const int vz  = blockIdx.z;
    const int v   = vz / NSEG, seg = vz % NSEG;
    const int ix  = blockIdx.x * 8 + threadIdx.x;
    const int iy  = blockIdx.y * 8 + threadIdx.y;
    const int tid = threadIdx.y * 8 + threadIdx.x;
    const int wid = tid >> 5, lane = tid & 31;
    const float X = (float)ix, Y = (float)iy;
    const float xmin = (float)(blockIdx.x * 8), xmax = xmin + 7.0f;
    const float ymin = (float)(blockIdx.y * 8), ymax = ymin + 7.0f;

    float T = 1.f;
    __shared__ float4 s0[BATCH + 4], s1[BATCH + 4];
    __shared__ unsigned sball[8];

    const int segbeg = seg * SEGLEN, segend = segbeg + SEGLEN;
    for (int base = segbeg; base < segend; base += BATCH) {
        int totalp = cull_batch(v, base, tid, wid, lane, xmin, xmax, ymin, ymax, s0, s1, sball);
        for (int j = 0; j < totalp; j += 4) {
#pragma unroll
            for (int u = 0; u < 4; u++) {
                float4 A = s0[j + u];
                float4 B = s1[j + u];
                float dx = X - A.x, dy = Y - A.y;
                float power = -0.5f * (A.z * dx * dx + B.x * dy * dy) - A.w * dx * dy;
                float al = fminf(0.99f, B.y * __expf(power));
                bool skip = (power > 0.f) || !(al >= ALPHA_MIN);
                T *= skip ? 1.f : (1.f - al);
            }
            // safe early out: recorded T >= true T but <= 1e-8 << T_EPS, so any
            // downstream prefix containing this factor still fails the gate.
            if (__all_sync(0xffffffffu, T < 1e-8f)) break;
        }
        if (__syncthreads_and(T < 1e-8f)) break;
    }
    g_T[v][seg][iy * IMW + ix] = T;
}

// ---------------------------------------------------------------------------
// Phase 3b: per-segment gated color accumulation starting at T_pre.
// ---------------------------------------------------------------------------
__global__ void __launch_bounds__(64) blend(const float* __restrict__ colors)
{
    const int vz  = blockIdx.z;
    const int v   = vz / NSEG, seg = vz % NSEG;
    const int ix  = blockIdx.x * 8 + threadIdx.x;
    const int iy  = blockIdx.y * 8 + threadIdx.y;
    const int tid = threadIdx.y * 8 + threadIdx.x;
    const int wid = tid >> 5, lane = tid & 31;
    const int pix = iy * IMW + ix;
    const float X = (float)ix, Y = (float)iy;
    const float xmin = (float)(blockIdx.x * 8), xmax = xmin + 7.0f;
    const float ymin = (float)(blockIdx.y * 8), ymax = ymin + 7.0f;

    float T = 1.f;
    for (int s = 0; s < NSEG - 1; s++)
        if (s < seg) T *= g_T[v][s][pix];

    float acc[NCH];
#pragma unroll
    for (int c = 0; c < NCH; c++) acc[c] = 0.f;
    float dacc = 0.f;

    __shared__ float4 s0[BATCH + 4], s1[BATCH + 4];
    __shared__ unsigned sball[8];

    // whole-CTA skip: every weight in this segment would be gated to 0
    if (!__syncthreads_and(T < T_EPS)) {
        const int segbeg = seg * SEGLEN, segend = segbeg + SEGLEN;
        for (int base = segbeg; base < segend; base += BATCH) {
            int totalp = cull_batch(v, base, tid, wid, lane, xmin, xmax, ymin, ymax, s0, s1, sball);
            for (int j = 0; j < totalp; j += 4) {
                float w4[4], tz4[4];
                int   id4[4];
#pragma unroll
                for (int u = 0; u < 4; u++) {
                    float4 A = s0[j + u];
                    float4 B = s1[j + u];
                    float dx = X - A.x, dy = Y - A.y;
                    float power = -0.5f * (A.z * dx * dx + B.x * dy * dy) - A.w * dx * dy;
                    float al = fminf(0.99f, B.y * __expf(power));
                    bool skip = (power > 0.f) || !(al >= ALPHA_MIN);
                    float ale = skip ? 0.f : al;
                    float Tn  = T * (1.f - ale);
                    w4[u]  = (Tn >= T_EPS) ? ale * T : 0.f;
                    tz4[u] = B.z;
                    id4[u] = __float_as_int(B.w);
                    T = Tn;
                }
#pragma unroll
                for (int u = 0; u < 4; u++) {
                    if (w4[u] != 0.f) {
                        float w = w4[u];
                        const float4* crow =
                            (const float4*)(colors + (size_t)((unsigned)id4[u]) * NCH);
#pragma unroll
                        for (int c4 = 0; c4 < 8; c4++) {
                            float4 cv = crow[c4];
                            acc[c4*4+0] += w * cv.x;
                            acc[c4*4+1] += w * cv.y;
                            acc[c4*4+2] += w * cv.z;
                            acc[c4*4+3] += w * cv.w;
                        }
                        dacc += w * tz4[u];
                    }
                }
                if (__all_sync(0xffffffffu, T < T_EPS)) break;
            }
            if (__syncthreads_and(T < T_EPS)) break;
        }
    }

#pragma unroll
    for (int c = 0; c < NCH; c++) g_part[v][seg][c][pix] = acc[c];
    g_part[v][seg][NCH][pix] = dacc;
}

// ---------------------------------------------------------------------------
// Phase 4: combine segment partials into the output.
// ---------------------------------------------------------------------------
__global__ void combine(float* __restrict__ out)
{
    int idx = blockIdx.x * 256 + threadIdx.x;
    if (idx >= NVIEW * (NCH + 1) * NPIX) return;
    int v   = idx / ((NCH + 1) * NPIX);
    int r   = idx % ((NCH + 1) * NPIX);
    int c   = r / NPIX;
    int pix = r % NPIX;
    float s = 0.f;
#pragma unroll
    for (int sg = 0; sg < NSEG; sg++) s += g_part[v][sg][c][pix];
    if (c < NCH) out[(size_t)(v * NCH + c) * NPIX + pix] = s;
    else         out[(size_t)NVIEW * NCH * NPIX + (size_t)v * NPIX + pix] = s;
}

// ---------------------------------------------------------------------------
extern "C" void kernel_launch(void* const* d_in, const int* in_sizes, int n_in,
                              void* d_out, int out_size)
{
    const float* means   = (const float*)d_in[0];
    const float* colors  = (const float*)d_in[1];
    const float* opac    = (const float*)d_in[2];
    const float* scales  = (const float*)d_in[3];
    const float* rots    = (const float*)d_in[4];
    const float* cam2img = (const float*)d_in[5];
    const float* cam2ego = (const float*)d_in[6];
    float* out = (float*)d_out;

    project<<<dim3(NVIEW, NGAUSS / 256), 256>>>(means, opac, scales, rots, cam2img, cam2ego);
    sortk<<<NVIEW, 1024>>>();
    transmit<<<dim3(IMW/8, IMH/8, NVIEW * NSEG), dim3(8, 8)>>>();
    blend   <<<dim3(IMW/8, IMH/8, NVIEW * NSEG), dim3(8, 8)>>>(colors);
    combine <<<(NVIEW * (NCH + 1) * NPIX + 255) / 256, 256>>>(out);
}

// round 8
// speedup vs baseline: 1.4806x; 1.0138x over previous
#include <cuda_runtime.h>

#define NGAUSS 2048
#define NCH    32
#define IMH    80
#define IMW    144
#define NPIX   (IMH*IMW)
#define NVIEW  2
#define NSEG   8
#define SEGLEN (NGAUSS/NSEG)
#define NEARP  0.2f
#define DILATE 0.3f
#define ALPHA_MIN (1.0f/255.0f)
#define T_EPS  1e-4f
#define BATCH  256   // gaussians culled per round (4 chunks of 64)

// unsorted per-gaussian attrs: [0]={px,py,ca,cb} [1]={cc,op,tz,idx} ; cull={px,py,rx,ry}
__device__ float4 g_attr  [NVIEW][NGAUSS][2];
__device__ float4 g_cullu [NVIEW][NGAUSS];
__device__ unsigned long long g_keys[NVIEW][NGAUSS];
// depth-sorted copies
__device__ float4 g_sorted[NVIEW][NGAUSS][2];
__device__ float4 g_cull  [NVIEW][NGAUSS];
// segmented compositing scratch
__device__ float g_T   [NVIEW][NSEG][NPIX];
__device__ float g_part[NVIEW][NSEG][NCH+1][NPIX];

// ---------------------------------------------------------------------------
// Phase 1: projection + conic + bbox radii. Wide grid.
// ---------------------------------------------------------------------------
__global__ void project(const float* __restrict__ means,
                        const float* __restrict__ opac,
                        const float* __restrict__ scales,
                        const float* __restrict__ rots,
                        const float* __restrict__ cam2img,
                        const float* __restrict__ cam2ego)
{
    const int v = blockIdx.x;
    const int n = blockIdx.y * 256 + threadIdx.x;
    if (n >= NGAUSS) return;

    const float* Km = cam2img + v * 9;
    const float* E  = cam2ego + v * 16;
    const float fx = Km[0], fy = Km[4], cx = Km[2], cy = Km[5];

    const float R00 = E[0], R01 = E[4], R02 = E[8];
    const float R10 = E[1], R11 = E[5], R12 = E[9];
    const float R20 = E[2], R21 = E[6], R22 = E[10];
    const float ex = E[3], ey = E[7], ez = E[11];
    const float Tx = -(R00*ex + R01*ey + R02*ez);
    const float Ty = -(R10*ex + R11*ey + R12*ez);
    const float Tz = -(R20*ex + R21*ey + R22*ez);
    const float tanfovx = (float)IMW * 0.5f / fx;
    const float tanfovy = (float)IMH * 0.5f / fy;

    float qw = rots[n*4+0], qx = rots[n*4+1], qy = rots[n*4+2], qz = rots[n*4+3];
    float inv = rsqrtf(qw*qw + qx*qx + qy*qy + qz*qz);
    qw *= inv; qx *= inv; qy *= inv; qz *= inv;
    float r00 = 1.f - 2.f*(qy*qy + qz*qz), r01 = 2.f*(qx*qy - qw*qz), r02 = 2.f*(qx*qz + qw*qy);
    float r10 = 2.f*(qx*qy + qw*qz), r11 = 1.f - 2.f*(qx*qx + qz*qz), r12 = 2.f*(qy*qz - qw*qx);
    float r20 = 2.f*(qx*qz - qw*qy), r21 = 2.f*(qy*qz + qw*qx), r22 = 1.f - 2.f*(qx*qx + qy*qy);

    float sx = scales[n*3+0], sy = scales[n*3+1], sz = scales[n*3+2];
    float m00 = r00*sx, m01 = r01*sy, m02 = r02*sz;
    float m10 = r10*sx, m11 = r11*sy, m12 = r12*sz;
    float m20 = r20*sx, m21 = r21*sy, m22 = r22*sz;

    float S00 = m00*m00 + m01*m01 + m02*m02;
    float S01 = m00*m10 + m01*m11 + m02*m12;
    float S02 = m00*m20 + m01*m21 + m02*m22;
    float S11 = m10*m10 + m11*m11 + m12*m12;
    float S12 = m10*m20 + m11*m21 + m12*m22;
    float S22 = m20*m20 + m21*m21 + m22*m22;

    float mx = means[n*3+0], my = means[n*3+1], mz = means[n*3+2];
    float tx = R00*mx + R01*my + R02*mz + Tx;
    float ty = R10*mx + R11*my + R12*mz + Ty;
    float tz = R20*mx + R21*my + R22*mz + Tz;

    bool  valid = tz > NEARP;
    float tzs   = valid ? tz : 1.0f;
    float txtz  = fminf(fmaxf(tx/tzs, -1.3f*tanfovx), 1.3f*tanfovx);
    float tytz  = fminf(fmaxf(ty/tzs, -1.3f*tanfovy), 1.3f*tanfovy);

    float A00 = R00*S00 + R01*S01 + R02*S02;
    float A01 = R00*S01 + R01*S11 + R02*S12;
    float A02 = R00*S02 + R01*S12 + R02*S22;
    float A10 = R10*S00 + R11*S01 + R12*S02;
    float A11 = R10*S01 + R11*S11 + R12*S12;
    float A12 = R10*S02 + R11*S12 + R12*S22;
    float A20 = R20*S00 + R21*S01 + R22*S02;
    float A21 = R20*S01 + R21*S11 + R22*S12;
    float A22 = R20*S02 + R21*S12 + R22*S22;
    float C00 = A00*R00 + A01*R01 + A02*R02;
    float C01 = A00*R10 + A01*R11 + A02*R12;
    float C02 = A00*R20 + A01*R21 + A02*R22;
    float C11 = A10*R10 + A11*R11 + A12*R12;
    float C12 = A10*R20 + A11*R21 + A12*R22;
    float C22 = A20*R20 + A21*R21 + A22*R22;

    float j00 = fx / tzs, j02 = -fx * txtz / tzs;
    float j11 = fy / tzs, j12 = -fy * tytz / tzs;
    float u0 = j00*C00 + j02*C02;
    float u1 = j00*C01 + j02*C12;
    float u2 = j00*C02 + j02*C22;
    float w1 = j11*C11 + j12*C12;
    float w2 = j11*C12 + j12*C22;
    float cov00 = u0*j00 + u2*j02;
    float cov01 = u1*j11 + u2*j12;
    float cov11 = w1*j11 + w2*j12;

    float a = cov00 + DILATE, b = cov01, c = cov11 + DILATE;
    float det = a*c - b*b;
    if (det == 0.f) det = 1.f;
    float ca = c / det, cb = -b / det, cc = a / det;

    float px = fx * tx / tzs + ((float)IMW - cx) - 0.5f;
    float py = fy * ty / tzs + ((float)IMH - cy) - 0.5f;
    float op = valid ? opac[n] : 0.f;

    // bbox radii of alpha >= 1/255 level set; NaN radii (op<=1/255) -> culled
    float t  = __logf(255.f * op);
    float rx = sqrtf(2.f * t * a) * 1.0001f + 1e-3f;
    float ry = sqrtf(2.f * t * c) * 1.0001f + 1e-3f;

    g_attr [v][n][0] = make_float4(px, py, ca, cb);
    g_attr [v][n][1] = make_float4(cc, op, tz, __int_as_float(n));
    g_cullu[v][n]    = make_float4(px, py, rx, ry);

    float keyf = valid ? tz : __int_as_float(0x7F800000);  // +inf
    g_keys[v][n] = (((unsigned long long)__float_as_uint(keyf)) << 32) | (unsigned)n;
}

// ---------------------------------------------------------------------------
// Phase 2: stable bitonic depth sort + gather. One CTA per view, 1024 threads.
// ---------------------------------------------------------------------------
__global__ void sortk()
{
    const int v   = blockIdx.x;
    const int tid = threadIdx.x;
    __shared__ unsigned long long keys[NGAUSS];

    keys[tid]        = g_keys[v][tid];
    keys[tid + 1024] = g_keys[v][tid + 1024];
    __syncthreads();

    unsigned prevj = 1;
    for (unsigned k = 2; k <= NGAUSS; k <<= 1) {
        for (unsigned j = k >> 1; j > 0; j >>= 1) {
            if (j >= 64 || prevj >= 64) __syncthreads(); else __syncwarp();
            unsigned t = tid;
            unsigned i   = ((t & ~(j - 1u)) << 1) | (t & (j - 1u));
            unsigned ixj = i | j;
            unsigned long long a0 = keys[i], b0 = keys[ixj];
            bool up = ((i & k) == 0);
            if ((a0 > b0) == up) { keys[i] = b0; keys[ixj] = a0; }
            prevj = j;
        }
    }
    __syncthreads();

    for (int i = tid; i < NGAUSS; i += 1024) {
        unsigned idx = (unsigned)(keys[i] & 0xFFFFFFFFu);
        g_sorted[v][i][0] = g_attr [v][idx][0];
        g_sorted[v][i][1] = g_attr [v][idx][1];
        g_cull  [v][i]    = g_cullu[v][idx];
    }
}

// ---------------------------------------------------------------------------
// Cooperative cull+compact of one BATCH into smem (depth order preserved).
// Returns padded count (multiple of 4), dummies have op=0.
// ---------------------------------------------------------------------------
__device__ __forceinline__ int cull_batch(int v, int base, int tid, int wid, int lane,
                                          float xmin, float xmax, float ymin, float ymax,
                                          float4* s0, float4* s1, unsigned* sball)
{
    const unsigned lmask = (1u << lane) - 1u;
    float4 cd[4];
#pragma unroll
    for (int k = 0; k < 4; k++) cd[k] = g_cull[v][base + k * 64 + tid];

    bool hit[4];
    unsigned myb[4];
#pragma unroll
    for (int k = 0; k < 4; k++) {
        hit[k] = (cd[k].x - cd[k].z <= xmax) && (cd[k].x + cd[k].z >= xmin) &&
                 (cd[k].y - cd[k].w <= ymax) && (cd[k].y + cd[k].w >= ymin);
        myb[k] = __ballot_sync(0xffffffffu, hit[k]);
    }
    if (lane == 0) {
#pragma unroll
        for (int k = 0; k < 4; k++) sball[k * 2 + wid] = myb[k];
    }
    __syncthreads();

    unsigned bl[8];
    int total = 0;
#pragma unroll
    for (int i = 0; i < 8; i++) { bl[i] = sball[i]; total += __popc(bl[i]); }

#pragma unroll
    for (int k = 0; k < 4; k++) {
        if (hit[k]) {
            int ord = k * 2 + wid;
            int off = 0;
            for (int i = 0; i < ord; i++) off += __popc(bl[i]);
            off += __popc(myb[k] & lmask);
            int g = base + k * 64 + tid;
            s0[off] = g_sorted[v][g][0];
            s1[off] = g_sorted[v][g][1];
        }
    }
    int pad = (4 - (total & 3)) & 3;
    if (tid < pad) {
        s0[total + tid] = make_float4(0.f, 0.f, 0.f, 0.f);
        s1[total + tid] = make_float4(0.f, 0.f, 0.f, 0.f);
    }
    __syncthreads();
    return total + pad;
}

// ---------------------------------------------------------------------------
// Phase 3a: per-segment transmittance (no color). grid z = v*NSEG+seg.
// ---------------------------------------------------------------------------
__global__ void __launch_bounds__(64) transmit()
{
    const int vz  = blockIdx.z;
    const int v   = vz / NSEG, seg = vz % NSEG;
    const int ix  = blockIdx.x * 8 + threadIdx.x;
    const int iy  = blockIdx.y * 8 + threadIdx.y;
    const int tid = threadIdx.y * 8 + threadIdx.x;
    const int wid = tid >> 5, lane = tid & 31;
    const float X = (float)ix, Y = (float)iy;
    const float xmin = (float)(blockIdx.x * 8), xmax = xmin + 7.0f;
    const float ymin = (float)(blockIdx.y * 8), ymax = ymin + 7.0f;

    float T = 1.f;
    __shared__ float4 s0[BATCH + 4], s1[BATCH + 4];
    __shared__ unsigned sball[8];

    const int segbeg = seg * SEGLEN, segend = segbeg + SEGLEN;
    for (int base = segbeg; base < segend; base += BATCH) {
        int totalp = cull_batch(v, base, tid, wid, lane, xmin, xmax, ymin, ymax, s0, s1, sball);
        for (int j = 0; j < totalp; j += 4) {
#pragma unroll
            for (int u = 0; u < 4; u++) {
                float4 A = s0[j + u];
                float4 B = s1[j + u];
                float dx = X - A.x, dy = Y - A.y;
                float power = -0.5f * (A.z * dx * dx + B.x * dy * dy) - A.w * dx * dy;
                float al = fminf(0.99f, B.y * __expf(power));
                bool skip = (power > 0.f) || !(al >= ALPHA_MIN);
                T *= skip ? 1.f : (1.f - al);
            }
            // safe early out: recorded T >= true T but <= 1e-8 << T_EPS, so any
            // downstream prefix containing this factor still fails the gate.
            if (__all_sync(0xffffffffu, T < 1e-8f)) break;
        }
        if (__syncthreads_and(T < 1e-8f)) break;
    }
    g_T[v][seg][iy * IMW + ix] = T;
}

// ---------------------------------------------------------------------------
// Phase 3b: per-segment gated color accumulation starting at T_pre.
// ---------------------------------------------------------------------------
__global__ void __launch_bounds__(64) blend(const float* __restrict__ colors)
{
    const int vz  = blockIdx.z;
    const int v   = vz / NSEG, seg = vz % NSEG;
    const int ix  = blockIdx.x * 8 + threadIdx.x;
    const int iy  = blockIdx.y * 8 + threadIdx.y;
    const int tid = threadIdx.y * 8 + threadIdx.x;
    const int wid = tid >> 5, lane = tid & 31;
    const int pix = iy * IMW + ix;
    const float X = (float)ix, Y = (float)iy;
    const float xmin = (float)(blockIdx.x * 8), xmax = xmin + 7.0f;
    const float ymin = (float)(blockIdx.y * 8), ymax = ymin + 7.0f;

    float T = 1.f;
#pragma unroll
    for (int s = 0; s < NSEG - 1; s++)
        if (s < seg) T *= g_T[v][s][pix];

    float acc[NCH];
#pragma unroll
    for (int c = 0; c < NCH; c++) acc[c] = 0.f;
    float dacc = 0.f;

    __shared__ float4 s0[BATCH + 4], s1[BATCH + 4];
    __shared__ unsigned sball[8];

    // whole-CTA skip: every weight in this segment would be gated to 0
    if (!__syncthreads_and(T < T_EPS)) {
        const int segbeg = seg * SEGLEN, segend = segbeg + SEGLEN;
        for (int base = segbeg; base < segend; base += BATCH) {
            int totalp = cull_batch(v, base, tid, wid, lane, xmin, xmax, ymin, ymax, s0, s1, sball);
            for (int j = 0; j < totalp; j += 4) {
                float w4[4], tz4[4];
                int   id4[4];
#pragma unroll
                for (int u = 0; u < 4; u++) {
                    float4 A = s0[j + u];
                    float4 B = s1[j + u];
                    float dx = X - A.x, dy = Y - A.y;
                    float power = -0.5f * (A.z * dx * dx + B.x * dy * dy) - A.w * dx * dy;
                    float al = fminf(0.99f, B.y * __expf(power));
                    bool skip = (power > 0.f) || !(al >= ALPHA_MIN);
                    float ale = skip ? 0.f : al;
                    float Tn  = T * (1.f - ale);
                    w4[u]  = (Tn >= T_EPS) ? ale * T : 0.f;
                    tz4[u] = B.z;
                    id4[u] = __float_as_int(B.w);
                    T = Tn;
                }
#pragma unroll
                for (int u = 0; u < 4; u++) {
                    if (w4[u] != 0.f) {
                        float w = w4[u];
                        const float4* crow =
                            (const float4*)(colors + (size_t)((unsigned)id4[u]) * NCH);
#pragma unroll
                        for (int c4 = 0; c4 < 8; c4++) {
                            float4 cv = crow[c4];
                            acc[c4*4+0] += w * cv.x;
                            acc[c4*4+1] += w * cv.y;
                            acc[c4*4+2] += w * cv.z;
                            acc[c4*4+3] += w * cv.w;
                        }
                        dacc += w * tz4[u];
                    }
                }
                if (__all_sync(0xffffffffu, T < T_EPS)) break;
            }
            if (__syncthreads_and(T < T_EPS)) break;
        }
    }

#pragma unroll
    for (int c = 0; c < NCH; c++) g_part[v][seg][c][pix] = acc[c];
    g_part[v][seg][NCH][pix] = dacc;
}

// ---------------------------------------------------------------------------
// Phase 4: combine segment partials into the output.
// ---------------------------------------------------------------------------
__global__ void combine(float* __restrict__ out)
{
    int idx = blockIdx.x * 256 + threadIdx.x;
    if (idx >= NVIEW * (NCH + 1) * NPIX) return;
    int v   = idx / ((NCH + 1) * NPIX);
    int r   = idx % ((NCH + 1) * NPIX);
    int c   = r / NPIX;
    int pix = r % NPIX;
    float s = 0.f;
#pragma unroll
    for (int sg = 0; sg < NSEG; sg++) s += g_part[v][sg][c][pix];
    if (c < NCH) out[(size_t)(v * NCH + c) * NPIX + pix] = s;
    else         out[(size_t)NVIEW * NCH * NPIX + (size_t)v * NPIX + pix] = s;
}

// ---------------------------------------------------------------------------
extern "C" void kernel_launch(void* const* d_in, const int* in_sizes, int n_in,
                              void* d_out, int out_size)
{
    const float* means   = (const float*)d_in[0];
    const float* colors  = (const float*)d_in[1];
    const float* opac    = (const float*)d_in[2];
    const float* scales  = (const float*)d_in[3];
    const float* rots    = (const float*)d_in[4];
    const float* cam2img = (const float*)d_in[5];
    const float* cam2ego = (const float*)d_in[6];
    float* out = (float*)d_out;

    project<<<dim3(NVIEW, NGAUSS / 256), 256>>>(means, opac, scales, rots, cam2img, cam2ego);
    sortk<<<NVIEW, 1024>>>();
    transmit<<<dim3(IMW/8, IMH/8, NVIEW * NSEG), dim3(8, 8)>>>();
    blend   <<<dim3(IMW/8, IMH/8, NVIEW * NSEG), dim3(8, 8)>>>(colors);
    combine <<<(NVIEW * (NCH + 1) * NPIX + 255) / 256, 256>>>(out);
}

// round 9
// speedup vs baseline: 1.5413x; 1.0410x over previous
#include <cuda_runtime.h>

#define NGAUSS 2048
#define NCH    32
#define IMH    80
#define IMW    144
#define NPIX   (IMH*IMW)
#define NTILEX (IMW/8)
#define NTILEY (IMH/8)
#define NTILE  (NTILEX*NTILEY)
#define NVIEW  2
#define NSEG   8
#define SEGLEN (NGAUSS/NSEG)
#define NEARP  0.2f
#define DILATE 0.3f
#define ALPHA_MIN (1.0f/255.0f)
#define T_EPS  1e-4f
#define BATCH  256   // == SEGLEN: one cull round per segment

// unsorted per-gaussian attrs: [0]={px,py,ca,cb} [1]={cc,op,tz,idx} ; cull={px,py,rx,ry}
__device__ float4 g_attr  [NVIEW][NGAUSS][2];
__device__ float4 g_cullu [NVIEW][NGAUSS];
__device__ unsigned long long g_keys[NVIEW][NGAUSS];
// depth-sorted copies
__device__ float4 g_sorted[NVIEW][NGAUSS][2];
__device__ float4 g_cull  [NVIEW][NGAUSS];
// segmented compositing scratch
__device__ float g_T[NVIEW][NSEG][NPIX];
// per-(view,seg,tile) compacted survivor lists (depth order, padded w/ dummies)
__device__ float4 g_list0[NVIEW][NSEG][NTILE][SEGLEN];
__device__ float4 g_list1[NVIEW][NSEG][NTILE][SEGLEN];
__device__ int    g_cnt  [NVIEW][NSEG][NTILE];

// ---------------------------------------------------------------------------
// Phase 0: zero the output (blend accumulates atomically into it).
// ---------------------------------------------------------------------------
__global__ void zero_out(float* __restrict__ out, int n)
{
    int i = blockIdx.x * 256 + threadIdx.x;
    if (i < n) out[i] = 0.f;
}

// ---------------------------------------------------------------------------
// Phase 1: projection + conic + bbox radii. Wide grid.
// ---------------------------------------------------------------------------
__global__ void project(const float* __restrict__ means,
                        const float* __restrict__ opac,
                        const float* __restrict__ scales,
                        const float* __restrict__ rots,
                        const float* __restrict__ cam2img,
                        const float* __restrict__ cam2ego)
{
    const int v = blockIdx.x;
    const int n = blockIdx.y * 256 + threadIdx.x;
    if (n >= NGAUSS) return;

    const float* Km = cam2img + v * 9;
    const float* E  = cam2ego + v * 16;
    const float fx = Km[0], fy = Km[4], cx = Km[2], cy = Km[5];

    const float R00 = E[0], R01 = E[4], R02 = E[8];
    const float R10 = E[1], R11 = E[5], R12 = E[9];
    const float R20 = E[2], R21 = E[6], R22 = E[10];
    const float ex = E[3], ey = E[7], ez = E[11];
    const float Tx = -(R00*ex + R01*ey + R02*ez);
    const float Ty = -(R10*ex + R11*ey + R12*ez);
    const float Tz = -(R20*ex + R21*ey + R22*ez);
    const float tanfovx = (float)IMW * 0.5f / fx;
    const float tanfovy = (float)IMH * 0.5f / fy;

    float qw = rots[n*4+0], qx = rots[n*4+1], qy = rots[n*4+2], qz = rots[n*4+3];
    float inv = rsqrtf(qw*qw + qx*qx + qy*qy + qz*qz);
    qw *= inv; qx *= inv; qy *= inv; qz *= inv;
    float r00 = 1.f - 2.f*(qy*qy + qz*qz), r01 = 2.f*(qx*qy - qw*qz), r02 = 2.f*(qx*qz + qw*qy);
    float r10 = 2.f*(qx*qy + qw*qz), r11 = 1.f - 2.f*(qx*qx + qz*qz), r12 = 2.f*(qy*qz - qw*qx);
    float r20 = 2.f*(qx*qz - qw*qy), r21 = 2.f*(qy*qz + qw*qx), r22 = 1.f - 2.f*(qx*qx + qy*qy);

    float sx = scales[n*3+0], sy = scales[n*3+1], sz = scales[n*3+2];
    float m00 = r00*sx, m01 = r01*sy, m02 = r02*sz;
    float m10 = r10*sx, m11 = r11*sy, m12 = r12*sz;
    float m20 = r20*sx, m21 = r21*sy, m22 = r22*sz;

    float S00 = m00*m00 + m01*m01 + m02*m02;
    float S01 = m00*m10 + m01*m11 + m02*m12;
    float S02 = m00*m20 + m01*m21 + m02*m22;
    float S11 = m10*m10 + m11*m11 + m12*m12;
    float S12 = m10*m20 + m11*m21 + m12*m22;
    float S22 = m20*m20 + m21*m21 + m22*m22;

    float mx = means[n*3+0], my = means[n*3+1], mz = means[n*3+2];
    float tx = R00*mx + R01*my + R02*mz + Tx;
    float ty = R10*mx + R11*my + R12*mz + Ty;
    float tz = R20*mx + R21*my + R22*mz + Tz;

    bool  valid = tz > NEARP;
    float tzs   = valid ? tz : 1.0f;
    float txtz  = fminf(fmaxf(tx/tzs, -1.3f*tanfovx), 1.3f*tanfovx);
    float tytz  = fminf(fmaxf(ty/tzs, -1.3f*tanfovy), 1.3f*tanfovy);

    float A00 = R00*S00 + R01*S01 + R02*S02;
    float A01 = R00*S01 + R01*S11 + R02*S12;
    float A02 = R00*S02 + R01*S12 + R02*S22;
    float A10 = R10*S00 + R11*S01 + R12*S02;
    float A11 = R10*S01 + R11*S11 + R12*S12;
    float A12 = R10*S02 + R11*S12 + R12*S22;
    float A20 = R20*S00 + R21*S01 + R22*S02;
    float A21 = R20*S01 + R21*S11 + R22*S12;
    float A22 = R20*S02 + R21*S12 + R22*S22;
    float C00 = A00*R00 + A01*R01 + A02*R02;
    float C01 = A00*R10 + A01*R11 + A02*R12;
    float C02 = A00*R20 + A01*R21 + A02*R22;
    float C11 = A10*R10 + A11*R11 + A12*R12;
    float C12 = A10*R20 + A11*R21 + A12*R22;
    float C22 = A20*R20 + A21*R21 + A22*R22;

    float j00 = fx / tzs, j02 = -fx * txtz / tzs;
    float j11 = fy / tzs, j12 = -fy * tytz / tzs;
    float u0 = j00*C00 + j02*C02;
    float u1 = j00*C01 + j02*C12;
    float u2 = j00*C02 + j02*C22;
    float w1 = j11*C11 + j12*C12;
    float w2 = j11*C12 + j12*C22;
    float cov00 = u0*j00 + u2*j02;
    float cov01 = u1*j11 + u2*j12;
    float cov11 = w1*j11 + w2*j12;

    float a = cov00 + DILATE, b = cov01, c = cov11 + DILATE;
    float det = a*c - b*b;
    if (det == 0.f) det = 1.f;
    float ca = c / det, cb = -b / det, cc = a / det;

    float px = fx * tx / tzs + ((float)IMW - cx) - 0.5f;
    float py = fy * ty / tzs + ((float)IMH - cy) - 0.5f;
    float op = valid ? opac[n] : 0.f;

    // bbox radii of alpha >= 1/255 level set; NaN radii (op<=1/255) -> culled
    float t  = __logf(255.f * op);
    float rx = sqrtf(2.f * t * a) * 1.0001f + 1e-3f;
    float ry = sqrtf(2.f * t * c) * 1.0001f + 1e-3f;

    g_attr [v][n][0] = make_float4(px, py, ca, cb);
    g_attr [v][n][1] = make_float4(cc, op, tz, __int_as_float(n));
    g_cullu[v][n]    = make_float4(px, py, rx, ry);

    float keyf = valid ? tz : __int_as_float(0x7F800000);  // +inf
    g_keys[v][n] = (((unsigned long long)__float_as_uint(keyf)) << 32) | (unsigned)n;
}

// ---------------------------------------------------------------------------
// Phase 2: stable bitonic depth sort + gather. One CTA per view, 1024 threads.
// ---------------------------------------------------------------------------
__global__ void sortk()
{
    const int v   = blockIdx.x;
    const int tid = threadIdx.x;
    __shared__ unsigned long long keys[NGAUSS];

    keys[tid]        = g_keys[v][tid];
    keys[tid + 1024] = g_keys[v][tid + 1024];
    __syncthreads();

    unsigned prevj = 1;
    for (unsigned k = 2; k <= NGAUSS; k <<= 1) {
        for (unsigned j = k >> 1; j > 0; j >>= 1) {
            if (j >= 64 || prevj >= 64) __syncthreads(); else __syncwarp();
            unsigned t = tid;
            unsigned i   = ((t & ~(j - 1u)) << 1) | (t & (j - 1u));
            unsigned ixj = i | j;
            unsigned long long a0 = keys[i], b0 = keys[ixj];
            bool up = ((i & k) == 0);
            if ((a0 > b0) == up) { keys[i] = b0; keys[ixj] = a0; }
            prevj = j;
        }
    }
    __syncthreads();

    for (int i = tid; i < NGAUSS; i += 1024) {
        unsigned idx = (unsigned)(keys[i] & 0xFFFFFFFFu);
        g_sorted[v][i][0] = g_attr [v][idx][0];
        g_sorted[v][i][1] = g_attr [v][idx][1];
        g_cull  [v][i]    = g_cullu[v][idx];
    }
}

// ---------------------------------------------------------------------------
// Phase 3a: transmit — per-(tile,seg) cull + compaction (persisted to gmem)
// and per-pixel segment transmittance. grid z = v*NSEG+seg.
// ---------------------------------------------------------------------------
__global__ void __launch_bounds__(64) transmit()
{
    const int vz   = blockIdx.z;
    const int v    = vz / NSEG, seg = vz % NSEG;
    const int tile = blockIdx.y * NTILEX + blockIdx.x;
    const int ix   = blockIdx.x * 8 + threadIdx.x;
    const int iy   = blockIdx.y * 8 + threadIdx.y;
    const int tid  = threadIdx.y * 8 + threadIdx.x;
    const int wid  = tid >> 5, lane = tid & 31;
    const float X = (float)ix, Y = (float)iy;
    const float xmin = (float)(blockIdx.x * 8), xmax = xmin + 7.0f;
    const float ymin = (float)(blockIdx.y * 8), ymax = ymin + 7.0f;
    const unsigned lmask = (1u << lane) - 1u;

    __shared__ float4 s0[BATCH + 4], s1[BATCH + 4];
    __shared__ unsigned sball[8];

    // ---- cull the single 256-gaussian batch of this segment ----
    const int base = seg * SEGLEN;
    float4 cd[4];
#pragma unroll
    for (int k = 0; k < 4; k++) cd[k] = g_cull[v][base + k * 64 + tid];

    bool hit[4];
    unsigned myb[4];
#pragma unroll
    for (int k = 0; k < 4; k++) {
        // NaN-safe: any NaN -> false -> culled
        hit[k] = (cd[k].x - cd[k].z <= xmax) && (cd[k].x + cd[k].z >= xmin) &&
                 (cd[k].y - cd[k].w <= ymax) && (cd[k].y + cd[k].w >= ymin);
        myb[k] = __ballot_sync(0xffffffffu, hit[k]);
    }
    if (lane == 0) {
#pragma unroll
        for (int k = 0; k < 4; k++) sball[k * 2 + wid] = myb[k];
    }
    __syncthreads();

    unsigned bl[8];
    int total = 0;
#pragma unroll
    for (int i = 0; i < 8; i++) { bl[i] = sball[i]; total += __popc(bl[i]); }

#pragma unroll
    for (int k = 0; k < 4; k++) {
        if (hit[k]) {
            int ord = k * 2 + wid;
            int off = 0;
            for (int i = 0; i < ord; i++) off += __popc(bl[i]);
            off += __popc(myb[k] & lmask);
            int g = base + k * 64 + tid;
            s0[off] = g_sorted[v][g][0];
            s1[off] = g_sorted[v][g][1];
        }
    }
    // pad to multiple of 4 with inert dummies (op=0 -> skip)
    int pad = (4 - (total & 3)) & 3;
    if (tid < pad) {
        s0[total + tid] = make_float4(0.f, 0.f, 0.f, 0.f);
        s1[total + tid] = make_float4(0.f, 0.f, 0.f, 0.f);
    }
    const int totalp = total + pad;
    __syncthreads();

    // ---- persist compacted list for blend ----
    for (int i = tid; i < totalp; i += 64) {
        g_list0[v][seg][tile][i] = s0[i];
        g_list1[v][seg][tile][i] = s1[i];
    }
    if (tid == 0) g_cnt[v][seg][tile] = totalp;

    // ---- per-pixel transmittance ----
    float T = 1.f;
    for (int j = 0; j < totalp; j += 4) {
#pragma unroll
        for (int u = 0; u < 4; u++) {
            float4 A = s0[j + u];
            float4 B = s1[j + u];
            float dx = X - A.x, dy = Y - A.y;
            float power = -0.5f * (A.z * dx * dx + B.x * dy * dy) - A.w * dx * dy;
            float al = fminf(0.99f, B.y * __expf(power));
            bool skip = (power > 0.f) || !(al >= ALPHA_MIN);
            T *= skip ? 1.f : (1.f - al);
        }
        // safe early out: recorded T >= true T but <= 1e-8 << T_EPS, so any
        // downstream prefix containing this factor still fails the gate.
        if (__all_sync(0xffffffffu, T < 1e-8f)) break;
    }
    g_T[v][seg][iy * IMW + ix] = T;
}

// ---------------------------------------------------------------------------
// Phase 3b: blend — gated color accumulation from the precompacted list,
// atomically added into the output.
// ---------------------------------------------------------------------------
__global__ void __launch_bounds__(64) blend(const float* __restrict__ colors,
                                            float* __restrict__ out)
{
    const int vz   = blockIdx.z;
    const int v    = vz / NSEG, seg = vz % NSEG;
    const int tile = blockIdx.y * NTILEX + blockIdx.x;
    const int ix   = blockIdx.x * 8 + threadIdx.x;
    const int iy   = blockIdx.y * 8 + threadIdx.y;
    const int tid  = threadIdx.y * 8 + threadIdx.x;
    const int pix  = iy * IMW + ix;
    const float X = (float)ix, Y = (float)iy;

    float T = 1.f;
#pragma unroll
    for (int s = 0; s < NSEG - 1; s++)
        if (s < seg) T *= g_T[v][s][pix];

    // whole-CTA skip: every weight in this segment would be gated to 0
    if (__syncthreads_and(T < T_EPS)) return;

    const int cnt = g_cnt[v][seg][tile];

    __shared__ float4 s0[SEGLEN + 4], s1[SEGLEN + 4];
    for (int i = tid; i < cnt; i += 64) {
        s0[i] = g_list0[v][seg][tile][i];
        s1[i] = g_list1[v][seg][tile][i];
    }
    __syncthreads();

    float acc[NCH];
#pragma unroll
    for (int c = 0; c < NCH; c++) acc[c] = 0.f;
    float dacc = 0.f;

    for (int j = 0; j < cnt; j += 4) {
        float w4[4], tz4[4];
        int   id4[4];
#pragma unroll
        for (int u = 0; u < 4; u++) {
            float4 A = s0[j + u];
            float4 B = s1[j + u];
            float dx = X - A.x, dy = Y - A.y;
            float power = -0.5f * (A.z * dx * dx + B.x * dy * dy) - A.w * dx * dy;
            float al = fminf(0.99f, B.y * __expf(power));
            bool skip = (power > 0.f) || !(al >= ALPHA_MIN);
            float ale = skip ? 0.f : al;
            float Tn  = T * (1.f - ale);
            w4[u]  = (Tn >= T_EPS) ? ale * T : 0.f;
            tz4[u] = B.z;
            id4[u] = __float_as_int(B.w);
            T = Tn;
        }
#pragma unroll
        for (int u = 0; u < 4; u++) {
            if (w4[u] != 0.f) {
                float w = w4[u];
                const float4* crow =
                    (const float4*)(colors + (size_t)((unsigned)id4[u]) * NCH);
#pragma unroll
                for (int c4 = 0; c4 < 8; c4++) {
                    float4 cv = crow[c4];
                    acc[c4*4+0] += w * cv.x;
                    acc[c4*4+1] += w * cv.y;
                    acc[c4*4+2] += w * cv.z;
                    acc[c4*4+3] += w * cv.w;
                }
                dacc += w * tz4[u];
            }
        }
        if (__all_sync(0xffffffffu, T < T_EPS)) break;
    }

    // dacc > 0 iff any weight was applied (w >= 3.9e-7, tz >= NEARP)
    if (dacc > 0.f) {
#pragma unroll
        for (int c = 0; c < NCH; c++)
            atomicAdd(&out[(size_t)(v * NCH + c) * NPIX + pix], acc[c]);
        atomicAdd(&out[(size_t)NVIEW * NCH * NPIX + (size_t)v * NPIX + pix], dacc);
    }
}

// ---------------------------------------------------------------------------
extern "C" void kernel_launch(void* const* d_in, const int* in_sizes, int n_in,
                              void* d_out, int out_size)
{
    const float* means   = (const float*)d_in[0];
    const float* colors  = (const float*)d_in[1];
    const float* opac    = (const float*)d_in[2];
    const float* scales  = (const float*)d_in[3];
    const float* rots    = (const float*)d_in[4];
    const float* cam2img = (const float*)d_in[5];
    const float* cam2ego = (const float*)d_in[6];
    float* out = (float*)d_out;

    zero_out<<<(out_size + 255) / 256, 256>>>(out, out_size);
    project<<<dim3(NVIEW, NGAUSS / 256), 256>>>(means, opac, scales, rots, cam2img, cam2ego);
    sortk<<<NVIEW, 1024>>>();
    transmit<<<dim3(NTILEX, NTILEY, NVIEW * NSEG), dim3(8, 8)>>>();
    blend   <<<dim3(NTILEX, NTILEY, NVIEW * NSEG), dim3(8, 8)>>>(colors, out);
}

// round 10
// speedup vs baseline: 1.6039x; 1.0406x over previous
#include <cuda_runtime.h>

#define NGAUSS 2048
#define NCH    32
#define IMH    80
#define IMW    144
#define NPIX   (IMH*IMW)
#define NTILEX (IMW/8)
#define NTILEY (IMH/8)
#define NTILE  (NTILEX*NTILEY)
#define NVIEW  2
#define NSEG   8
#define SEGLEN (NGAUSS/NSEG)
#define NEARP  0.2f
#define DILATE 0.3f
#define ALPHA_MIN (1.0f/255.0f)
#define T_EPS  1e-4f
#define BATCH  256   // == SEGLEN: one cull round per segment

// unsorted per-gaussian attrs: [0]={px,py,ca,cb} [1]={cc,op,tz,idx} ; cull={px,py,rx,ry}
__device__ float4 g_attr  [NVIEW][NGAUSS][2];
__device__ float4 g_cullu [NVIEW][NGAUSS];
__device__ unsigned long long g_keys[NVIEW][NGAUSS];
// depth-sorted copies
__device__ float4 g_sorted[NVIEW][NGAUSS][2];
__device__ float4 g_cull  [NVIEW][NGAUSS];
// segmented compositing scratch
__device__ float  g_T    [NVIEW][NSEG][NPIX];
__device__ float2 g_list [NVIEW][NSEG][NTILE][SEGLEN];      // {tz, idx_bits}
__device__ int    g_cnt  [NVIEW][NSEG][NTILE];
// per-(survivor, pixel) effective alpha, written by transmit, read by blend
__device__ float  g_alpha[NVIEW][NSEG][NTILE][SEGLEN][64];

// ---------------------------------------------------------------------------
// Phase 1: projection + conic + bbox radii. Wide grid.
// ---------------------------------------------------------------------------
__global__ void project(const float* __restrict__ means,
                        const float* __restrict__ opac,
                        const float* __restrict__ scales,
                        const float* __restrict__ rots,
                        const float* __restrict__ cam2img,
                        const float* __restrict__ cam2ego)
{
    const int v = blockIdx.x;
    const int n = blockIdx.y * 256 + threadIdx.x;
    if (n >= NGAUSS) return;

    const float* Km = cam2img + v * 9;
    const float* E  = cam2ego + v * 16;
    const float fx = Km[0], fy = Km[4], cx = Km[2], cy = Km[5];

    const float R00 = E[0], R01 = E[4], R02 = E[8];
    const float R10 = E[1], R11 = E[5], R12 = E[9];
    const float R20 = E[2], R21 = E[6], R22 = E[10];
    const float ex = E[3], ey = E[7], ez = E[11];
    const float Tx = -(R00*ex + R01*ey + R02*ez);
    const float Ty = -(R10*ex + R11*ey + R12*ez);
    const float Tz = -(R20*ex + R21*ey + R22*ez);
    const float tanfovx = (float)IMW * 0.5f / fx;
    const float tanfovy = (float)IMH * 0.5f / fy;

    float qw = rots[n*4+0], qx = rots[n*4+1], qy = rots[n*4+2], qz = rots[n*4+3];
    float inv = rsqrtf(qw*qw + qx*qx + qy*qy + qz*qz);
    qw *= inv; qx *= inv; qy *= inv; qz *= inv;
    float r00 = 1.f - 2.f*(qy*qy + qz*qz), r01 = 2.f*(qx*qy - qw*qz), r02 = 2.f*(qx*qz + qw*qy);
    float r10 = 2.f*(qx*qy + qw*qz), r11 = 1.f - 2.f*(qx*qx + qz*qz), r12 = 2.f*(qy*qz - qw*qx);
    float r20 = 2.f*(qx*qz - qw*qy), r21 = 2.f*(qy*qz + qw*qx), r22 = 1.f - 2.f*(qx*qx + qy*qy);

    float sx = scales[n*3+0], sy = scales[n*3+1], sz = scales[n*3+2];
    float m00 = r00*sx, m01 = r01*sy, m02 = r02*sz;
    float m10 = r10*sx, m11 = r11*sy, m12 = r12*sz;
    float m20 = r20*sx, m21 = r21*sy, m22 = r22*sz;

    float S00 = m00*m00 + m01*m01 + m02*m02;
    float S01 = m00*m10 + m01*m11 + m02*m12;
    float S02 = m00*m20 + m01*m21 + m02*m22;
    float S11 = m10*m10 + m11*m11 + m12*m12;
    float S12 = m10*m20 + m11*m21 + m12*m22;
    float S22 = m20*m20 + m21*m21 + m22*m22;

    float mx = means[n*3+0], my = means[n*3+1], mz = means[n*3+2];
    float tx = R00*mx + R01*my + R02*mz + Tx;
    float ty = R10*mx + R11*my + R12*mz + Ty;
    float tz = R20*mx + R21*my + R22*mz + Tz;

    bool  valid = tz > NEARP;
    float tzs   = valid ? tz : 1.0f;
    float txtz  = fminf(fmaxf(tx/tzs, -1.3f*tanfovx), 1.3f*tanfovx);
    float tytz  = fminf(fmaxf(ty/tzs, -1.3f*tanfovy), 1.3f*tanfovy);

    float A00 = R00*S00 + R01*S01 + R02*S02;
    float A01 = R00*S01 + R01*S11 + R02*S12;
    float A02 = R00*S02 + R01*S12 + R02*S22;
    float A10 = R10*S00 + R11*S01 + R12*S02;
    float A11 = R10*S01 + R11*S11 + R12*S12;
    float A12 = R10*S02 + R11*S12 + R12*S22;
    float A20 = R20*S00 + R21*S01 + R22*S02;
    float A21 = R20*S01 + R21*S11 + R22*S12;
    float A22 = R20*S02 + R21*S12 + R22*S22;
    float C00 = A00*R00 + A01*R01 + A02*R02;
    float C01 = A00*R10 + A01*R11 + A02*R12;
    float C02 = A00*R20 + A01*R21 + A02*R22;
    float C11 = A10*R10 + A11*R11 + A12*R12;
    float C12 = A10*R20 + A11*R21 + A12*R22;
    float C22 = A20*R20 + A21*R21 + A22*R22;

    float j00 = fx / tzs, j02 = -fx * txtz / tzs;
    float j11 = fy / tzs, j12 = -fy * tytz / tzs;
    float u0 = j00*C00 + j02*C02;
    float u1 = j00*C01 + j02*C12;
    float u2 = j00*C02 + j02*C22;
    float w1 = j11*C11 + j12*C12;
    float w2 = j11*C12 + j12*C22;
    float cov00 = u0*j00 + u2*j02;
    float cov01 = u1*j11 + u2*j12;
    float cov11 = w1*j11 + w2*j12;

    float a = cov00 + DILATE, b = cov01, c = cov11 + DILATE;
    float det = a*c - b*b;
    if (det == 0.f) det = 1.f;
    float ca = c / det, cb = -b / det, cc = a / det;

    float px = fx * tx / tzs + ((float)IMW - cx) - 0.5f;
    float py = fy * ty / tzs + ((float)IMH - cy) - 0.5f;
    float op = valid ? opac[n] : 0.f;

    // bbox radii of alpha >= 1/255 level set; NaN radii (op<=1/255) -> culled
    float t  = __logf(255.f * op);
    float rx = sqrtf(2.f * t * a) * 1.0001f + 1e-3f;
    float ry = sqrtf(2.f * t * c) * 1.0001f + 1e-3f;

    g_attr [v][n][0] = make_float4(px, py, ca, cb);
    g_attr [v][n][1] = make_float4(cc, op, tz, __int_as_float(n));
    g_cullu[v][n]    = make_float4(px, py, rx, ry);

    float keyf = valid ? tz : __int_as_float(0x7F800000);  // +inf
    g_keys[v][n] = (((unsigned long long)__float_as_uint(keyf)) << 32) | (unsigned)n;
}

// ---------------------------------------------------------------------------
// Phase 2: stable bitonic depth sort + gather. One CTA per view, 1024 threads.
// ---------------------------------------------------------------------------
__global__ void sortk()
{
    const int v   = blockIdx.x;
    const int tid = threadIdx.x;
    __shared__ unsigned long long keys[NGAUSS];

    keys[tid]        = g_keys[v][tid];
    keys[tid + 1024] = g_keys[v][tid + 1024];
    __syncthreads();

    unsigned prevj = 1;
    for (unsigned k = 2; k <= NGAUSS; k <<= 1) {
        for (unsigned j = k >> 1; j > 0; j >>= 1) {
            if (j >= 64 || prevj >= 64) __syncthreads(); else __syncwarp();
            unsigned t = tid;
            unsigned i   = ((t & ~(j - 1u)) << 1) | (t & (j - 1u));
            unsigned ixj = i | j;
            unsigned long long a0 = keys[i], b0 = keys[ixj];
            bool up = ((i & k) == 0);
            if ((a0 > b0) == up) { keys[i] = b0; keys[ixj] = a0; }
            prevj = j;
        }
    }
    __syncthreads();

    for (int i = tid; i < NGAUSS; i += 1024) {
        unsigned idx = (unsigned)(keys[i] & 0xFFFFFFFFu);
        g_sorted[v][i][0] = g_attr [v][idx][0];
        g_sorted[v][i][1] = g_attr [v][idx][1];
        g_cull  [v][i]    = g_cullu[v][idx];
    }
}

// ---------------------------------------------------------------------------
// Phase 3a: transmit — cull + compaction, per-(survivor,pixel) alpha store,
// per-pixel segment transmittance. Also zeroes the output chunkwise
// (removes the separate zero kernel; blend's atomics depend on it).
// ---------------------------------------------------------------------------
__global__ void __launch_bounds__(64) transmit(float* __restrict__ out, int out_count)
{
    const int vz   = blockIdx.z;
    const int v    = vz / NSEG, seg = vz % NSEG;
    const int tile = blockIdx.y * NTILEX + blockIdx.x;
    const int ix   = blockIdx.x * 8 + threadIdx.x;
    const int iy   = blockIdx.y * 8 + threadIdx.y;
    const int tid  = threadIdx.y * 8 + threadIdx.x;
    const int wid  = tid >> 5, lane = tid & 31;
    const float X = (float)ix, Y = (float)iy;
    const float xmin = (float)(blockIdx.x * 8), xmax = xmin + 7.0f;
    const float ymin = (float)(blockIdx.y * 8), ymax = ymin + 7.0f;
    const unsigned lmask = (1u << lane) - 1u;

    // ---- zero my chunk of the output ----
    {
        const int ngrid = NTILE * NVIEW * NSEG;
        const int chunk = (out_count + ngrid - 1) / ngrid;
        const int base  = (vz * NTILE + tile) * chunk;
        for (int i = tid; i < chunk; i += 64) {
            int o = base + i;
            if (o < out_count) out[o] = 0.f;
        }
    }

    __shared__ float4 s0[BATCH + 4], s1[BATCH + 4];
    __shared__ unsigned sball[8];

    // ---- cull the single 256-gaussian batch of this segment ----
    const int base = seg * SEGLEN;
    float4 cd[4];
#pragma unroll
    for (int k = 0; k < 4; k++) cd[k] = g_cull[v][base + k * 64 + tid];

    bool hit[4];
    unsigned myb[4];
#pragma unroll
    for (int k = 0; k < 4; k++) {
        // NaN-safe: any NaN -> false -> culled
        hit[k] = (cd[k].x - cd[k].z <= xmax) && (cd[k].x + cd[k].z >= xmin) &&
                 (cd[k].y - cd[k].w <= ymax) && (cd[k].y + cd[k].w >= ymin);
        myb[k] = __ballot_sync(0xffffffffu, hit[k]);
    }
    if (lane == 0) {
#pragma unroll
        for (int k = 0; k < 4; k++) sball[k * 2 + wid] = myb[k];
    }
    __syncthreads();

    unsigned bl[8];
    int total = 0;
#pragma unroll
    for (int i = 0; i < 8; i++) { bl[i] = sball[i]; total += __popc(bl[i]); }

#pragma unroll
    for (int k = 0; k < 4; k++) {
        if (hit[k]) {
            int ord = k * 2 + wid;
            int off = 0;
            for (int i = 0; i < ord; i++) off += __popc(bl[i]);
            off += __popc(myb[k] & lmask);
            int g = base + k * 64 + tid;
            s0[off] = g_sorted[v][g][0];
            s1[off] = g_sorted[v][g][1];
        }
    }
    // pad to multiple of 4 with inert dummies (op=0 -> alpha 0)
    int pad = (4 - (total & 3)) & 3;
    if (tid < pad) {
        s0[total + tid] = make_float4(0.f, 0.f, 0.f, 0.f);
        s1[total + tid] = make_float4(0.f, 0.f, 0.f, 0.f);
    }
    const int totalp = total + pad;
    __syncthreads();

    // ---- persist {tz, idx} list for blend ----
    for (int i = tid; i < totalp; i += 64) {
        float4 t = s1[i];
        g_list[v][seg][tile][i] = make_float2(t.z, t.w);
    }
    if (tid == 0) g_cnt[v][seg][tile] = totalp;

    // ---- per-pixel transmittance + alpha store ----
    float T = 1.f;
    float* ap = &g_alpha[v][seg][tile][0][0];
    for (int j = 0; j < totalp; j += 4) {
#pragma unroll
        for (int u = 0; u < 4; u++) {
            float4 A = s0[j + u];
            float4 B = s1[j + u];
            float dx = X - A.x, dy = Y - A.y;
            float power = -0.5f * (A.z * dx * dx + B.x * dy * dy) - A.w * dx * dy;
            float al = fminf(0.99f, B.y * __expf(power));
            bool skip = (power > 0.f) || !(al >= ALPHA_MIN);
            float ale = skip ? 0.f : al;
            T *= 1.f - ale;
            ap[(j + u) * 64 + tid] = ale;   // coalesced 256B store per survivor
        }
        // safe early out: break boundary is strictly tighter (1e-8) than
        // blend's gate (1e-4) and checked at the same j, same warp mapping,
        // so blend provably breaks at or before the last written group.
        if (__all_sync(0xffffffffu, T < 1e-8f)) break;
    }
    g_T[v][seg][iy * IMW + ix] = T;
}

// ---------------------------------------------------------------------------
// Phase 3b: blend — gated color accumulation from precomputed alphas,
// atomically added into the output.
// ---------------------------------------------------------------------------
__global__ void __launch_bounds__(64) blend(const float* __restrict__ colors,
                                            float* __restrict__ out)
{
    const int vz   = blockIdx.z;
    const int v    = vz / NSEG, seg = vz % NSEG;
    const int tile = blockIdx.y * NTILEX + blockIdx.x;
    const int ix   = blockIdx.x * 8 + threadIdx.x;
    const int iy   = blockIdx.y * 8 + threadIdx.y;
    const int tid  = threadIdx.y * 8 + threadIdx.x;
    const int pix  = iy * IMW + ix;

    float T = 1.f;
#pragma unroll
    for (int s = 0; s < NSEG - 1; s++)
        if (s < seg) T *= g_T[v][s][pix];

    // whole-CTA skip: every weight in this segment would be gated to 0
    if (__syncthreads_and(T < T_EPS)) return;

    const int cnt = g_cnt[v][seg][tile];

    __shared__ float2 sl[SEGLEN + 4];
    for (int i = tid; i < cnt; i += 64) sl[i] = g_list[v][seg][tile][i];
    __syncthreads();

    float acc[NCH];
#pragma unroll
    for (int c = 0; c < NCH; c++) acc[c] = 0.f;
    float dacc = 0.f;

    const float* ap = &g_alpha[v][seg][tile][0][0];
    for (int j = 0; j < cnt; j += 4) {
        float a4[4];
#pragma unroll
        for (int u = 0; u < 4; u++) a4[u] = ap[(j + u) * 64 + tid];

        float w4[4];
#pragma unroll
        for (int u = 0; u < 4; u++) {
            float ale = a4[u];
            float Tn  = T * (1.f - ale);
            w4[u] = (Tn >= T_EPS) ? ale * T : 0.f;
            T = Tn;
        }
#pragma unroll
        for (int u = 0; u < 4; u++) {
            if (w4[u] != 0.f) {
                float w = w4[u];
                float2 li = sl[j + u];
                const float4* crow =
                    (const float4*)(colors + (size_t)((unsigned)__float_as_int(li.y)) * NCH);
#pragma unroll
                for (int c4 = 0; c4 < 8; c4++) {
                    float4 cv = crow[c4];
                    acc[c4*4+0] += w * cv.x;
                    acc[c4*4+1] += w * cv.y;
                    acc[c4*4+2] += w * cv.z;
                    acc[c4*4+3] += w * cv.w;
                }
                dacc += w * li.x;
            }
        }
        if (__all_sync(0xffffffffu, T < T_EPS)) break;   // per-warp; no smem reuse
    }

    // dacc > 0 iff any weight was applied (w >= 3.9e-7, tz >= NEARP)
    if (dacc > 0.f) {
#pragma unroll
        for (int c = 0; c < NCH; c++)
            atomicAdd(&out[(size_t)(v * NCH + c) * NPIX + pix], acc[c]);
        atomicAdd(&out[(size_t)NVIEW * NCH * NPIX + (size_t)v * NPIX + pix], dacc);
    }
}

// ---------------------------------------------------------------------------
extern "C" void kernel_launch(void* const* d_in, const int* in_sizes, int n_in,
                              void* d_out, int out_size)
{
    const float* means   = (const float*)d_in[0];
    const float* colors  = (const float*)d_in[1];
    const float* opac    = (const float*)d_in[2];
    const float* scales  = (const float*)d_in[3];
    const float* rots    = (const float*)d_in[4];
    const float* cam2img = (const float*)d_in[5];
    const float* cam2ego = (const float*)d_in[6];
    float* out = (float*)d_out;

    project<<<dim3(NVIEW, NGAUSS / 256), 256>>>(means, opac, scales, rots, cam2img, cam2ego);
    sortk<<<NVIEW, 1024>>>();
    transmit<<<dim3(NTILEX, NTILEY, NVIEW * NSEG), dim3(8, 8)>>>(out, out_size);
    blend   <<<dim3(NTILEX, NTILEY, NVIEW * NSEG), dim3(8, 8)>>>(colors, out);
}

// round 11
// speedup vs baseline: 1.6778x; 1.0460x over previous
#include <cuda_runtime.h>

#define NGAUSS 2048
#define NCH    32
#define IMH    80
#define IMW    144
#define NPIX   (IMH*IMW)
#define NTILEX (IMW/8)
#define NTILEY (IMH/8)
#define NTILE  (NTILEX*NTILEY)
#define NVIEW  2
#define NSEG   8
#define SEGLEN (NGAUSS/NSEG)
#define NEARP  0.2f
#define DILATE 0.3f
#define ALPHA_MIN (1.0f/255.0f)
#define T_EPS  1e-4f
#define BATCH  256   // == SEGLEN: one cull round per segment

// unsorted per-gaussian attrs: [0]={px,py,ca,cb} [1]={cc,op,tz,idx} ; cull={px,py,rx,ry}
__device__ float4 g_attr  [NVIEW][NGAUSS][2];
__device__ float4 g_cullu [NVIEW][NGAUSS];
// depth-sorted copies
__device__ float4 g_sorted[NVIEW][NGAUSS][2];
__device__ float4 g_cull  [NVIEW][NGAUSS];
// segmented compositing scratch
__device__ float  g_T    [NVIEW][NSEG][NPIX];
__device__ float4 g_list0[NVIEW][NSEG][NTILE][SEGLEN];
__device__ float4 g_list1[NVIEW][NSEG][NTILE][SEGLEN];
__device__ int    g_cnt  [NVIEW][NSEG][NTILE];

// ---------------------------------------------------------------------------
// Phase 1: fused projection + conic + bbox radii + stable bitonic depth sort.
// One CTA per view, 1024 threads; bitonic steps with j<=32 are warp-local.
// ---------------------------------------------------------------------------
__global__ void prep_sort(const float* __restrict__ means,
                          const float* __restrict__ opac,
                          const float* __restrict__ scales,
                          const float* __restrict__ rots,
                          const float* __restrict__ cam2img,
                          const float* __restrict__ cam2ego)
{
    const int v   = blockIdx.x;
    const int tid = threadIdx.x;
    __shared__ unsigned long long keys[NGAUSS];

    const float* Km = cam2img + v * 9;
    const float* E  = cam2ego + v * 16;
    const float fx = Km[0], fy = Km[4], cx = Km[2], cy = Km[5];

    const float R00 = E[0], R01 = E[4], R02 = E[8];
    const float R10 = E[1], R11 = E[5], R12 = E[9];
    const float R20 = E[2], R21 = E[6], R22 = E[10];
    const float ex = E[3], ey = E[7], ez = E[11];
    const float Tx = -(R00*ex + R01*ey + R02*ez);
    const float Ty = -(R10*ex + R11*ey + R12*ez);
    const float Tz = -(R20*ex + R21*ey + R22*ez);
    const float tanfovx = (float)IMW * 0.5f / fx;
    const float tanfovy = (float)IMH * 0.5f / fy;

    for (int n = tid; n < NGAUSS; n += 1024) {
        float qw = rots[n*4+0], qx = rots[n*4+1], qy = rots[n*4+2], qz = rots[n*4+3];
        float inv = rsqrtf(qw*qw + qx*qx + qy*qy + qz*qz);
        qw *= inv; qx *= inv; qy *= inv; qz *= inv;
        float r00 = 1.f - 2.f*(qy*qy + qz*qz), r01 = 2.f*(qx*qy - qw*qz), r02 = 2.f*(qx*qz + qw*qy);
        float r10 = 2.f*(qx*qy + qw*qz), r11 = 1.f - 2.f*(qx*qx + qz*qz), r12 = 2.f*(qy*qz - qw*qx);
        float r20 = 2.f*(qx*qz - qw*qy), r21 = 2.f*(qy*qz + qw*qx), r22 = 1.f - 2.f*(qx*qx + qy*qy);

        float sx = scales[n*3+0], sy = scales[n*3+1], sz = scales[n*3+2];
        float m00 = r00*sx, m01 = r01*sy, m02 = r02*sz;
        float m10 = r10*sx, m11 = r11*sy, m12 = r12*sz;
        float m20 = r20*sx, m21 = r21*sy, m22 = r22*sz;

        float S00 = m00*m00 + m01*m01 + m02*m02;
        float S01 = m00*m10 + m01*m11 + m02*m12;
        float S02 = m00*m20 + m01*m21 + m02*m22;
        float S11 = m10*m10 + m11*m11 + m12*m12;
        float S12 = m10*m20 + m11*m21 + m12*m22;
        float S22 = m20*m20 + m21*m21 + m22*m22;

        float mx = means[n*3+0], my = means[n*3+1], mz = means[n*3+2];
        float tx = R00*mx + R01*my + R02*mz + Tx;
        float ty = R10*mx + R11*my + R12*mz + Ty;
        float tz = R20*mx + R21*my + R22*mz + Tz;

        bool  valid = tz > NEARP;
        float tzs   = valid ? tz : 1.0f;
        float txtz  = fminf(fmaxf(tx/tzs, -1.3f*tanfovx), 1.3f*tanfovx);
        float tytz  = fminf(fmaxf(ty/tzs, -1.3f*tanfovy), 1.3f*tanfovy);

        float A00 = R00*S00 + R01*S01 + R02*S02;
        float A01 = R00*S01 + R01*S11 + R02*S12;
        float A02 = R00*S02 + R01*S12 + R02*S22;
        float A10 = R10*S00 + R11*S01 + R12*S02;
        float A11 = R10*S01 + R11*S11 + R12*S12;
        float A12 = R10*S02 + R11*S12 + R12*S22;
        float A20 = R20*S00 + R21*S01 + R22*S02;
        float A21 = R20*S01 + R21*S11 + R22*S12;
        float A22 = R20*S02 + R21*S12 + R22*S22;
        float C00 = A00*R00 + A01*R01 + A02*R02;
        float C01 = A00*R10 + A01*R11 + A02*R12;
        float C02 = A00*R20 + A01*R21 + A02*R22;
        float C11 = A10*R10 + A11*R11 + A12*R12;
        float C12 = A10*R20 + A11*R21 + A12*R22;
        float C22 = A20*R20 + A21*R21 + A22*R22;

        float j00 = fx / tzs, j02 = -fx * txtz / tzs;
        float j11 = fy / tzs, j12 = -fy * tytz / tzs;
        float u0 = j00*C00 + j02*C02;
        float u1 = j00*C01 + j02*C12;
        float u2 = j00*C02 + j02*C22;
        float w1 = j11*C11 + j12*C12;
        float w2 = j11*C12 + j12*C22;
        float cov00 = u0*j00 + u2*j02;
        float cov01 = u1*j11 + u2*j12;
        float cov11 = w1*j11 + w2*j12;

        float a = cov00 + DILATE, b = cov01, c = cov11 + DILATE;
        float det = a*c - b*b;
        if (det == 0.f) det = 1.f;
        float ca = c / det, cb = -b / det, cc = a / det;

        float px = fx * tx / tzs + ((float)IMW - cx) - 0.5f;
        float py = fy * ty / tzs + ((float)IMH - cy) - 0.5f;
        float op = valid ? opac[n] : 0.f;

        // bbox radii of alpha >= 1/255 level set; NaN radii (op<=1/255) -> culled
        float t  = __logf(255.f * op);
        float rx = sqrtf(2.f * t * a) * 1.0001f + 1e-3f;
        float ry = sqrtf(2.f * t * c) * 1.0001f + 1e-3f;

        g_attr [v][n][0] = make_float4(px, py, ca, cb);
        g_attr [v][n][1] = make_float4(cc, op, tz, __int_as_float(n));
        g_cullu[v][n]    = make_float4(px, py, rx, ry);

        float keyf = valid ? tz : __int_as_float(0x7F800000);  // +inf
        keys[n] = (((unsigned long long)__float_as_uint(keyf)) << 32) | (unsigned)n;
    }
    __syncthreads();

    // bitonic, ascending; idx in low bits => stable (matches jnp.argsort).
    // warp w exclusively owns keys[64w..64w+64) for all steps with j <= 32.
    unsigned prevj = 1;
    for (unsigned k = 2; k <= NGAUSS; k <<= 1) {
        for (unsigned j = k >> 1; j > 0; j >>= 1) {
            if (j >= 64 || prevj >= 64) __syncthreads(); else __syncwarp();
            unsigned t = tid;
            unsigned i   = ((t & ~(j - 1u)) << 1) | (t & (j - 1u));
            unsigned ixj = i | j;
            unsigned long long a0 = keys[i], b0 = keys[ixj];
            bool up = ((i & k) == 0);
            if ((a0 > b0) == up) { keys[i] = b0; keys[ixj] = a0; }
            prevj = j;
        }
    }
    __syncthreads();

    for (int i = tid; i < NGAUSS; i += 1024) {
        unsigned idx = (unsigned)(keys[i] & 0xFFFFFFFFu);
        g_sorted[v][i][0] = g_attr [v][idx][0];
        g_sorted[v][i][1] = g_attr [v][idx][1];
        g_cull  [v][i]    = g_cullu[v][idx];
    }
}

// ---------------------------------------------------------------------------
// Phase 2: transmit — cull + compaction (persisted), per-pixel segment
// transmittance. Also zeroes the output chunkwise (blend atomics depend on it).
// ---------------------------------------------------------------------------
__global__ void __launch_bounds__(64) transmit(float* __restrict__ out, int out_count)
{
    const int vz   = blockIdx.z;
    const int v    = vz / NSEG, seg = vz % NSEG;
    const int tile = blockIdx.y * NTILEX + blockIdx.x;
    const int ix   = blockIdx.x * 8 + threadIdx.x;
    const int iy   = blockIdx.y * 8 + threadIdx.y;
    const int tid  = threadIdx.y * 8 + threadIdx.x;
    const int wid  = tid >> 5, lane = tid & 31;
    const float X = (float)ix, Y = (float)iy;
    const float xmin = (float)(blockIdx.x * 8), xmax = xmin + 7.0f;
    const float ymin = (float)(blockIdx.y * 8), ymax = ymin + 7.0f;
    const unsigned lmask = (1u << lane) - 1u;

    // ---- zero my chunk of the output ----
    {
        const int ngrid = NTILE * NVIEW * NSEG;
        const int chunk = (out_count + ngrid - 1) / ngrid;
        const int base  = (vz * NTILE + tile) * chunk;
        for (int i = tid; i < chunk; i += 64) {
            int o = base + i;
            if (o < out_count) out[o] = 0.f;
        }
    }

    __shared__ float4 s0[BATCH + 4], s1[BATCH + 4];
    __shared__ unsigned sball[8];

    // ---- cull the single 256-gaussian batch of this segment ----
    const int base = seg * SEGLEN;
    float4 cd[4];
#pragma unroll
    for (int k = 0; k < 4; k++) cd[k] = g_cull[v][base + k * 64 + tid];

    bool hit[4];
    unsigned myb[4];
#pragma unroll
    for (int k = 0; k < 4; k++) {
        // NaN-safe: any NaN -> false -> culled
        hit[k] = (cd[k].x - cd[k].z <= xmax) && (cd[k].x + cd[k].z >= xmin) &&
                 (cd[k].y - cd[k].w <= ymax) && (cd[k].y + cd[k].w >= ymin);
        myb[k] = __ballot_sync(0xffffffffu, hit[k]);
    }
    if (lane == 0) {
#pragma unroll
        for (int k = 0; k < 4; k++) sball[k * 2 + wid] = myb[k];
    }
    __syncthreads();

    unsigned bl[8];
    int total = 0;
#pragma unroll
    for (int i = 0; i < 8; i++) { bl[i] = sball[i]; total += __popc(bl[i]); }

#pragma unroll
    for (int k = 0; k < 4; k++) {
        if (hit[k]) {
            int ord = k * 2 + wid;
            int off = 0;
            for (int i = 0; i < ord; i++) off += __popc(bl[i]);
            off += __popc(myb[k] & lmask);
            int g = base + k * 64 + tid;
            s0[off] = g_sorted[v][g][0];
            s1[off] = g_sorted[v][g][1];
        }
    }
    // pad to multiple of 4 with inert dummies (op=0 -> alpha 0)
    int pad = (4 - (total & 3)) & 3;
    if (tid < pad) {
        s0[total + tid] = make_float4(0.f, 0.f, 0.f, 0.f);
        s1[total + tid] = make_float4(0.f, 0.f, 0.f, 0.f);
    }
    const int totalp = total + pad;
    __syncthreads();

    // ---- persist compacted list for blend ----
    for (int i = tid; i < totalp; i += 64) {
        g_list0[v][seg][tile][i] = s0[i];
        g_list1[v][seg][tile][i] = s1[i];
    }
    if (tid == 0) g_cnt[v][seg][tile] = totalp;

    // ---- per-pixel transmittance ----
    float T = 1.f;
    for (int j = 0; j < totalp; j += 4) {
#pragma unroll
        for (int u = 0; u < 4; u++) {
            float4 A = s0[j + u];
            float4 B = s1[j + u];
            float dx = X - A.x, dy = Y - A.y;
            float power = -0.5f * (A.z * dx * dx + B.x * dy * dy) - A.w * dx * dy;
            float al = fminf(0.99f, B.y * __expf(power));
            bool skip = (power > 0.f) || !(al >= ALPHA_MIN);
            T *= skip ? 1.f : (1.f - al);
        }
        // safe early out: recorded T >= true T but <= 1e-8 << T_EPS, so any
        // downstream prefix containing this factor still fails the gate.
        if (__all_sync(0xffffffffu, T < 1e-8f)) break;
    }
    g_T[v][seg][iy * IMW + ix] = T;
}

// ---------------------------------------------------------------------------
// Phase 3: blend — gated color accumulation from the precompacted list.
// Channel-split: grid z = (v*NSEG+seg)*2 + half; each CTA does 16 channels.
// ---------------------------------------------------------------------------
__global__ void __launch_bounds__(64) blend(const float* __restrict__ colors,
                                            float* __restrict__ out)
{
    const int vzh  = blockIdx.z;
    const int half = vzh & 1;
    const int vz   = vzh >> 1;
    const int v    = vz / NSEG, seg = vz % NSEG;
    const int tile = blockIdx.y * NTILEX + blockIdx.x;
    const int ix   = blockIdx.x * 8 + threadIdx.x;
    const int iy   = blockIdx.y * 8 + threadIdx.y;
    const int tid  = threadIdx.y * 8 + threadIdx.x;
    const int pix  = iy * IMW + ix;
    const float X = (float)ix, Y = (float)iy;

    float T = 1.f;
#pragma unroll
    for (int s = 0; s < NSEG - 1; s++)
        if (s < seg) T *= g_T[v][s][pix];

    // whole-CTA skip: every weight in this segment would be gated to 0
    if (__syncthreads_and(T < T_EPS)) return;

    const int cnt = g_cnt[v][seg][tile];

    __shared__ float4 s0[SEGLEN + 4], s1[SEGLEN + 4];
    for (int i = tid; i < cnt; i += 64) {
        s0[i] = g_list0[v][seg][tile][i];
        s1[i] = g_list1[v][seg][tile][i];
    }
    __syncthreads();

    float acc[16];
#pragma unroll
    for (int c = 0; c < 16; c++) acc[c] = 0.f;
    float dacc = 0.f;
    bool applied = false;

    for (int j = 0; j < cnt; j += 4) {
        float w4[4], tz4[4];
        int   id4[4];
#pragma unroll
        for (int u = 0; u < 4; u++) {
            float4 A = s0[j + u];
            float4 B = s1[j + u];
            float dx = X - A.x, dy = Y - A.y;
            float power = -0.5f * (A.z * dx * dx + B.x * dy * dy) - A.w * dx * dy;
            float al = fminf(0.99f, B.y * __expf(power));
            bool skip = (power > 0.f) || !(al >= ALPHA_MIN);
            float ale = skip ? 0.f : al;
            float Tn  = T * (1.f - ale);
            w4[u]  = (Tn >= T_EPS) ? ale * T : 0.f;
            tz4[u] = B.z;
            id4[u] = __float_as_int(B.w);
            T = Tn;
        }
#pragma unroll
        for (int u = 0; u < 4; u++) {
            if (w4[u] != 0.f) {
                applied = true;
                float w = w4[u];
                const float4* crow = (const float4*)
                    (colors + (size_t)((unsigned)id4[u]) * NCH + half * 16);
#pragma unroll
                for (int c4 = 0; c4 < 4; c4++) {
                    float4 cv = crow[c4];
                    acc[c4*4+0] += w * cv.x;
                    acc[c4*4+1] += w * cv.y;
                    acc[c4*4+2] += w * cv.z;
                    acc[c4*4+3] += w * cv.w;
                }
                dacc += w * tz4[u];
            }
        }
        if (__all_sync(0xffffffffu, T < T_EPS)) break;   // per-warp; no smem reuse
    }

    if (applied) {
#pragma unroll
        for (int c = 0; c < 16; c++)
            atomicAdd(&out[(size_t)(v * NCH + half * 16 + c) * NPIX + pix], acc[c]);
        if (half == 0)
            atomicAdd(&out[(size_t)NVIEW * NCH * NPIX + (size_t)v * NPIX + pix], dacc);
    }
}

// ---------------------------------------------------------------------------
extern "C" void kernel_launch(void* const* d_in, const int* in_sizes, int n_in,
                              void* d_out, int out_size)
{
    const float* means   = (const float*)d_in[0];
    const float* colors  = (const float*)d_in[1];
    const float* opac    = (const float*)d_in[2];
    const float* scales  = (const float*)d_in[3];
    const float* rots    = (const float*)d_in[4];
    const float* cam2img = (const float*)d_in[5];
    const float* cam2ego = (const float*)d_in[6];
    float* out = (float*)d_out;

    prep_sort<<<NVIEW, 1024>>>(means, opac, scales, rots, cam2img, cam2ego);
    transmit<<<dim3(NTILEX, NTILEY, NVIEW * NSEG), dim3(8, 8)>>>(out, out_size);
    blend   <<<dim3(NTILEX, NTILEY, NVIEW * NSEG * 2), dim3(8, 8)>>>(colors, out);
}

// round 12
// speedup vs baseline: 1.9611x; 1.1689x over previous
#include <cuda_runtime.h>

#define NGAUSS 2048
#define NCH    32
#define IMH    80
#define IMW    144
#define NPIX   (IMH*IMW)
#define NTILEX (IMW/8)
#define NTILEY (IMH/8)
#define NTILE  (NTILEX*NTILEY)
#define NVIEW  2
#define NSEG   8
#define SEGLEN (NGAUSS/NSEG)
#define NEARP  0.2f
#define DILATE 0.3f
#define ALPHA_MIN (1.0f/255.0f)
#define T_EPS  1e-4f
#define BATCH  256   // == SEGLEN: one cull round per segment

// unsorted per-gaussian attrs: [0]={px,py,ca,cb} [1]={cc,op,tz,idx} ; cull={px,py,rx,ry}
__device__ float4 g_attr  [NVIEW][NGAUSS][2];
__device__ float4 g_cullu [NVIEW][NGAUSS];
__device__ unsigned long long g_keys[NVIEW][NGAUSS];
// depth-sorted copies
__device__ float4 g_sorted[NVIEW][NGAUSS][2];
__device__ float4 g_cull  [NVIEW][NGAUSS];
// segmented compositing scratch
__device__ float  g_T    [NVIEW][NSEG][NPIX];
__device__ float4 g_list0[NVIEW][NSEG][NTILE][SEGLEN];
__device__ float4 g_list1[NVIEW][NSEG][NTILE][SEGLEN];
__device__ int    g_cnt  [NVIEW][NSEG][NTILE];

// ---------------------------------------------------------------------------
// Phase 1: projection + conic + bbox radii. Wide grid.
// ---------------------------------------------------------------------------
__global__ void project(const float* __restrict__ means,
                        const float* __restrict__ opac,
                        const float* __restrict__ scales,
                        const float* __restrict__ rots,
                        const float* __restrict__ cam2img,
                        const float* __restrict__ cam2ego)
{
    const int v = blockIdx.x;
    const int n = blockIdx.y * 256 + threadIdx.x;
    if (n >= NGAUSS) return;

    const float* Km = cam2img + v * 9;
    const float* E  = cam2ego + v * 16;
    const float fx = Km[0], fy = Km[4], cx = Km[2], cy = Km[5];

    const float R00 = E[0], R01 = E[4], R02 = E[8];
    const float R10 = E[1], R11 = E[5], R12 = E[9];
    const float R20 = E[2], R21 = E[6], R22 = E[10];
    const float ex = E[3], ey = E[7], ez = E[11];
    const float Tx = -(R00*ex + R01*ey + R02*ez);
    const float Ty = -(R10*ex + R11*ey + R12*ez);
    const float Tz = -(R20*ex + R21*ey + R22*ez);
    const float tanfovx = (float)IMW * 0.5f / fx;
    const float tanfovy = (float)IMH * 0.5f / fy;

    float qw = rots[n*4+0], qx = rots[n*4+1], qy = rots[n*4+2], qz = rots[n*4+3];
    float inv = rsqrtf(qw*qw + qx*qx + qy*qy + qz*qz);
    qw *= inv; qx *= inv; qy *= inv; qz *= inv;
    float r00 = 1.f - 2.f*(qy*qy + qz*qz), r01 = 2.f*(qx*qy - qw*qz), r02 = 2.f*(qx*qz + qw*qy);
    float r10 = 2.f*(qx*qy + qw*qz), r11 = 1.f - 2.f*(qx*qx + qz*qz), r12 = 2.f*(qy*qz - qw*qx);
    float r20 = 2.f*(qx*qz - qw*qy), r21 = 2.f*(qy*qz + qw*qx), r22 = 1.f - 2.f*(qx*qx + qy*qy);

    float sx = scales[n*3+0], sy = scales[n*3+1], sz = scales[n*3+2];
    float m00 = r00*sx, m01 = r01*sy, m02 = r02*sz;
    float m10 = r10*sx, m11 = r11*sy, m12 = r12*sz;
    float m20 = r20*sx, m21 = r21*sy, m22 = r22*sz;

    float S00 = m00*m00 + m01*m01 + m02*m02;
    float S01 = m00*m10 + m01*m11 + m02*m12;
    float S02 = m00*m20 + m01*m21 + m02*m22;
    float S11 = m10*m10 + m11*m11 + m12*m12;
    float S12 = m10*m20 + m11*m21 + m12*m22;
    float S22 = m20*m20 + m21*m21 + m22*m22;

    float mx = means[n*3+0], my = means[n*3+1], mz = means[n*3+2];
    float tx = R00*mx + R01*my + R02*mz + Tx;
    float ty = R10*mx + R11*my + R12*mz + Ty;
    float tz = R20*mx + R21*my + R22*mz + Tz;

    bool  valid = tz > NEARP;
    float tzs   = valid ? tz : 1.0f;
    float txtz  = fminf(fmaxf(tx/tzs, -1.3f*tanfovx), 1.3f*tanfovx);
    float tytz  = fminf(fmaxf(ty/tzs, -1.3f*tanfovy), 1.3f*tanfovy);

    float A00 = R00*S00 + R01*S01 + R02*S02;
    float A01 = R00*S01 + R01*S11 + R02*S12;
    float A02 = R00*S02 + R01*S12 + R02*S22;
    float A10 = R10*S00 + R11*S01 + R12*S02;
    float A11 = R10*S01 + R11*S11 + R12*S12;
    float A12 = R10*S02 + R11*S12 + R12*S22;
    float A20 = R20*S00 + R21*S01 + R22*S02;
    float A21 = R20*S01 + R21*S11 + R22*S12;
    float A22 = R20*S02 + R21*S12 + R22*S22;
    float C00 = A00*R00 + A01*R01 + A02*R02;
    float C01 = A00*R10 + A01*R11 + A02*R12;
    float C02 = A00*R20 + A01*R21 + A02*R22;
    float C11 = A10*R10 + A11*R11 + A12*R12;
    float C12 = A10*R20 + A11*R21 + A12*R22;
    float C22 = A20*R20 + A21*R21 + A22*R22;

    float j00 = fx / tzs, j02 = -fx * txtz / tzs;
    float j11 = fy / tzs, j12 = -fy * tytz / tzs;
    float u0 = j00*C00 + j02*C02;
    float u1 = j00*C01 + j02*C12;
    float u2 = j00*C02 + j02*C22;
    float w1 = j11*C11 + j12*C12;
    float w2 = j11*C12 + j12*C22;
    float cov00 = u0*j00 + u2*j02;
    float cov01 = u1*j11 + u2*j12;
    float cov11 = w1*j11 + w2*j12;

    float a = cov00 + DILATE, b = cov01, c = cov11 + DILATE;
    float det = a*c - b*b;
    if (det == 0.f) det = 1.f;
    float ca = c / det, cb = -b / det, cc = a / det;

    float px = fx * tx / tzs + ((float)IMW - cx) - 0.5f;
    float py = fy * ty / tzs + ((float)IMH - cy) - 0.5f;
    float op = valid ? opac[n] : 0.f;

    // bbox radii of alpha >= 1/255 level set; NaN radii (op<=1/255) -> culled
    float t  = __logf(255.f * op);
    float rx = sqrtf(2.f * t * a) * 1.0001f + 1e-3f;
    float ry = sqrtf(2.f * t * c) * 1.0001f + 1e-3f;

    g_attr [v][n][0] = make_float4(px, py, ca, cb);
    g_attr [v][n][1] = make_float4(cc, op, tz, __int_as_float(n));
    g_cullu[v][n]    = make_float4(px, py, rx, ry);

    float keyf = valid ? tz : __int_as_float(0x7F800000);  // +inf
    g_keys[v][n] = (((unsigned long long)__float_as_uint(keyf)) << 32) | (unsigned)n;
}

// ---------------------------------------------------------------------------
// Phase 2: enumeration (rank) sort + scatter. Keys are unique, so
// rank(e) = #{j : key_j < key_e} is a stable ascending permutation —
// identical result to a stable sort by (tz, idx). grid (NVIEW, 16) x 256:
// each CTA ranks 128 elements; 2 threads per element count one half each
// using broadcast smem reads (all lanes in a warp read the same key).
// ---------------------------------------------------------------------------
__global__ void __launch_bounds__(256) rank_scatter()
{
    const int v     = blockIdx.x;
    const int t     = threadIdx.x;
    const int e_loc = t & 127;
    const int h     = t >> 7;                 // which half of the keys I count
    const int e     = blockIdx.y * 128 + e_loc;

    __shared__ unsigned long long sk[NGAUSS];
    __shared__ int scnt[128];

    for (int i = t; i < NGAUSS; i += 256) sk[i] = g_keys[v][i];
    if (t < 128) scnt[t] = 0;
    __syncthreads();

    const unsigned long long ke = sk[e];
    int cnt = 0;
    const int base = h * (NGAUSS / 2);
#pragma unroll 16
    for (int s = 0; s < NGAUSS / 2; s++)
        cnt += (sk[base + s] < ke) ? 1 : 0;
    atomicAdd(&scnt[e_loc], cnt);
    __syncthreads();

    if (t < 128) {
        int r = scnt[t];
        g_sorted[v][r][0] = g_attr [v][e][0];
        g_sorted[v][r][1] = g_attr [v][e][1];
        g_cull  [v][r]    = g_cullu[v][e];
    }
}

// ---------------------------------------------------------------------------
// Phase 3: transmit — cull + compaction (persisted), per-pixel segment
// transmittance. Also zeroes the output chunkwise (blend atomics depend on it).
// ---------------------------------------------------------------------------
__global__ void __launch_bounds__(64) transmit(float* __restrict__ out, int out_count)
{
    const int vz   = blockIdx.z;
    const int v    = vz / NSEG, seg = vz % NSEG;
    const int tile = blockIdx.y * NTILEX + blockIdx.x;
    const int ix   = blockIdx.x * 8 + threadIdx.x;
    const int iy   = blockIdx.y * 8 + threadIdx.y;
    const int tid  = threadIdx.y * 8 + threadIdx.x;
    const int wid  = tid >> 5, lane = tid & 31;
    const float X = (float)ix, Y = (float)iy;
    const float xmin = (float)(blockIdx.x * 8), xmax = xmin + 7.0f;
    const float ymin = (float)(blockIdx.y * 8), ymax = ymin + 7.0f;
    const unsigned lmask = (1u << lane) - 1u;

    // ---- zero my chunk of the output ----
    {
        const int ngrid = NTILE * NVIEW * NSEG;
        const int chunk = (out_count + ngrid - 1) / ngrid;
        const int base  = (vz * NTILE + tile) * chunk;
        for (int i = tid; i < chunk; i += 64) {
            int o = base + i;
            if (o < out_count) out[o] = 0.f;
        }
    }

    __shared__ float4 s0[BATCH + 4], s1[BATCH + 4];
    __shared__ unsigned sball[8];

    // ---- cull the single 256-gaussian batch of this segment ----
    const int base = seg * SEGLEN;
    float4 cd[4];
#pragma unroll
    for (int k = 0; k < 4; k++) cd[k] = g_cull[v][base + k * 64 + tid];

    bool hit[4];
    unsigned myb[4];
#pragma unroll
    for (int k = 0; k < 4; k++) {
        // NaN-safe: any NaN -> false -> culled
        hit[k] = (cd[k].x - cd[k].z <= xmax) && (cd[k].x + cd[k].z >= xmin) &&
                 (cd[k].y - cd[k].w <= ymax) && (cd[k].y + cd[k].w >= ymin);
        myb[k] = __ballot_sync(0xffffffffu, hit[k]);
    }
    if (lane == 0) {
#pragma unroll
        for (int k = 0; k < 4; k++) sball[k * 2 + wid] = myb[k];
    }
    __syncthreads();

    unsigned bl[8];
    int total = 0;
#pragma unroll
    for (int i = 0; i < 8; i++) { bl[i] = sball[i]; total += __popc(bl[i]); }

#pragma unroll
    for (int k = 0; k < 4; k++) {
        if (hit[k]) {
            int ord = k * 2 + wid;
            int off = 0;
            for (int i = 0; i < ord; i++) off += __popc(bl[i]);
            off += __popc(myb[k] & lmask);
            int g = base + k * 64 + tid;
            s0[off] = g_sorted[v][g][0];
            s1[off] = g_sorted[v][g][1];
        }
    }
    // pad to multiple of 4 with inert dummies (op=0 -> alpha 0)
    int pad = (4 - (total & 3)) & 3;
    if (tid < pad) {
        s0[total + tid] = make_float4(0.f, 0.f, 0.f, 0.f);
        s1[total + tid] = make_float4(0.f, 0.f, 0.f, 0.f);
    }
    const int totalp = total + pad;
    __syncthreads();

    // ---- persist compacted list for blend ----
    for (int i = tid; i < totalp; i += 64) {
        g_list0[v][seg][tile][i] = s0[i];
        g_list1[v][seg][tile][i] = s1[i];
    }
    if (tid == 0) g_cnt[v][seg][tile] = totalp;

    // ---- per-pixel transmittance ----
    float T = 1.f;
    for (int j = 0; j < totalp; j += 4) {
#pragma unroll
        for (int u = 0; u < 4; u++) {
            float4 A = s0[j + u];
            float4 B = s1[j + u];
            float dx = X - A.x, dy = Y - A.y;
            float power = -0.5f * (A.z * dx * dx + B.x * dy * dy) - A.w * dx * dy;
            float al = fminf(0.99f, B.y * __expf(power));
            bool skip = (power > 0.f) || !(al >= ALPHA_MIN);
            T *= skip ? 1.f : (1.f - al);
        }
        // safe early out: recorded T >= true T but <= 1e-8 << T_EPS, so any
        // downstream prefix containing this factor still fails the gate.
        if (__all_sync(0xffffffffu, T < 1e-8f)) break;
    }
    g_T[v][seg][iy * IMW + ix] = T;
}

// ---------------------------------------------------------------------------
// Phase 4: blend — gated color accumulation from the precompacted list.
// Channel-split: grid z = (v*NSEG+seg)*2 + half; each CTA does 16 channels.
// ---------------------------------------------------------------------------
__global__ void __launch_bounds__(64) blend(const float* __restrict__ colors,
                                            float* __restrict__ out)
{
    const int vzh  = blockIdx.z;
    const int half = vzh & 1;
    const int vz   = vzh >> 1;
    const int v    = vz / NSEG, seg = vz % NSEG;
    const int tile = blockIdx.y * NTILEX + blockIdx.x;
    const int ix   = blockIdx.x * 8 + threadIdx.x;
    const int iy   = blockIdx.y * 8 + threadIdx.y;
    const int tid  = threadIdx.y * 8 + threadIdx.x;
    const int pix  = iy * IMW + ix;
    const float X = (float)ix, Y = (float)iy;

    float T = 1.f;
#pragma unroll
    for (int s = 0; s < NSEG - 1; s++)
        if (s < seg) T *= g_T[v][s][pix];

    // whole-CTA skip: every weight in this segment would be gated to 0
    if (__syncthreads_and(T < T_EPS)) return;

    const int cnt = g_cnt[v][seg][tile];

    __shared__ float4 s0[SEGLEN + 4], s1[SEGLEN + 4];
    for (int i = tid; i < cnt; i += 64) {
        s0[i] = g_list0[v][seg][tile][i];
        s1[i] = g_list1[v][seg][tile][i];
    }
    __syncthreads();

    float acc[16];
#pragma unroll
    for (int c = 0; c < 16; c++) acc[c] = 0.f;
    float dacc = 0.f;
    bool applied = false;

    for (int j = 0; j < cnt; j += 4) {
        float w4[4], tz4[4];
        int   id4[4];
#pragma unroll
        for (int u = 0; u < 4; u++) {
            float4 A = s0[j + u];
            float4 B = s1[j + u];
            float dx = X - A.x, dy = Y - A.y;
            float power = -0.5f * (A.z * dx * dx + B.x * dy * dy) - A.w * dx * dy;
            float al = fminf(0.99f, B.y * __expf(power));
            bool skip = (power > 0.f) || !(al >= ALPHA_MIN);
            float ale = skip ? 0.f : al;
            float Tn  = T * (1.f - ale);
            w4[u]  = (Tn >= T_EPS) ? ale * T : 0.f;
            tz4[u] = B.z;
            id4[u] = __float_as_int(B.w);
            T = Tn;
        }
#pragma unroll
        for (int u = 0; u < 4; u++) {
            if (w4[u] != 0.f) {
                applied = true;
                float w = w4[u];
                const float4* crow = (const float4*)
                    (colors + (size_t)((unsigned)id4[u]) * NCH + half * 16);
#pragma unroll
                for (int c4 = 0; c4 < 4; c4++) {
                    float4 cv = crow[c4];
                    acc[c4*4+0] += w * cv.x;
                    acc[c4*4+1] += w * cv.y;
                    acc[c4*4+2] += w * cv.z;
                    acc[c4*4+3] += w * cv.w;
                }
                dacc += w * tz4[u];
            }
        }
        if (__all_sync(0xffffffffu, T < T_EPS)) break;   // per-warp; no smem reuse
    }

    if (applied) {
#pragma unroll
        for (int c = 0; c < 16; c++)
            atomicAdd(&out[(size_t)(v * NCH + half * 16 + c) * NPIX + pix], acc[c]);
        if (half == 0)
            atomicAdd(&out[(size_t)NVIEW * NCH * NPIX + (size_t)v * NPIX + pix], dacc);
    }
}

// ---------------------------------------------------------------------------
extern "C" void kernel_launch(void* const* d_in, const int* in_sizes, int n_in,
                              void* d_out, int out_size)
{
    const float* means   = (const float*)d_in[0];
    const float* colors  = (const float*)d_in[1];
    const float* opac    = (const float*)d_in[2];
    const float* scales  = (const float*)d_in[3];
    const float* rots    = (const float*)d_in[4];
    const float* cam2img = (const float*)d_in[5];
    const float* cam2ego = (const float*)d_in[6];
    float* out = (float*)d_out;

    project<<<dim3(NVIEW, NGAUSS / 256), 256>>>(means, opac, scales, rots, cam2img, cam2ego);
    rank_scatter<<<dim3(NVIEW, NGAUSS / 128), 256>>>();
    transmit<<<dim3(NTILEX, NTILEY, NVIEW * NSEG), dim3(8, 8)>>>(out, out_size);
    blend   <<<dim3(NTILEX, NTILEY, NVIEW * NSEG * 2), dim3(8, 8)>>>(colors, out);
}

// round 13
// speedup vs baseline: 2.0059x; 1.0229x over previous
#include <cuda_runtime.h>

#define NGAUSS 2048
#define NCH    32
#define IMH    80
#define IMW    144
#define NPIX   (IMH*IMW)
#define NTILEX (IMW/8)
#define NTILEY (IMH/8)
#define NTILE  (NTILEX*NTILEY)
#define NVIEW  2
#define NSEG   8
#define SEGLEN (NGAUSS/NSEG)
#define NEARP  0.2f
#define DILATE 0.3f
#define ALPHA_MIN (1.0f/255.0f)
#define T_EPS  1e-4f
#define BATCH  256   // == SEGLEN: one cull round per segment

// depth-sorted per-gaussian attrs: [0]={px,py,ca,cb} [1]={cc,op,tz,idx} ; cull={px,py,rx,ry}
__device__ float4 g_sorted[NVIEW][NGAUSS][2];
__device__ float4 g_cull  [NVIEW][NGAUSS];
// segmented compositing scratch
__device__ float  g_T    [NVIEW][NSEG][NPIX];
__device__ float4 g_list0[NVIEW][NSEG][NTILE][SEGLEN];
__device__ float4 g_list1[NVIEW][NSEG][NTILE][SEGLEN];
__device__ int    g_cnt  [NVIEW][NSEG][NTILE];

// ---------------------------------------------------------------------------
// Phase 1: fused projection + enumeration(rank) sort + scatter.
// grid (NVIEW, NGAUSS/128) x 256. Each CTA:
//   - computes ALL 2048 sort keys locally (tz needs only one rotation row),
//   - fully projects its own 128 elements (held in registers, half-0 threads),
//   - ranks each element with 2 threads counting one half of the keys each
//     (broadcast smem reads), and scatters directly to the sorted arrays.
// Keys are unique 64-bit (tz_bits<<32)|idx, so rank = #{key_j < key_e} is a
// stable ascending permutation == jnp.argsort. No inter-CTA dependencies.
// ---------------------------------------------------------------------------
__global__ void __launch_bounds__(256) prep(const float* __restrict__ means,
                                            const float* __restrict__ opac,
                                            const float* __restrict__ scales,
                                            const float* __restrict__ rots,
                                            const float* __restrict__ cam2img,
                                            const float* __restrict__ cam2ego)
{
    const int v     = blockIdx.x;
    const int t     = threadIdx.x;
    const int e_loc = t & 127;
    const int h     = t >> 7;                 // which half of the keys I count
    const int e     = blockIdx.y * 128 + e_loc;

    __shared__ unsigned long long sk[NGAUSS];
    __shared__ int scnt[128];

    const float* Km = cam2img + v * 9;
    const float* E  = cam2ego + v * 16;
    const float fx = Km[0], fy = Km[4], cx = Km[2], cy = Km[5];

    const float R00 = E[0], R01 = E[4], R02 = E[8];
    const float R10 = E[1], R11 = E[5], R12 = E[9];
    const float R20 = E[2], R21 = E[6], R22 = E[10];
    const float ex = E[3], ey = E[7], ez = E[11];
    const float Tx = -(R00*ex + R01*ey + R02*ez);
    const float Ty = -(R10*ex + R11*ey + R12*ez);
    const float Tz = -(R20*ex + R21*ey + R22*ez);
    const float tanfovx = (float)IMW * 0.5f / fx;
    const float tanfovy = (float)IMH * 0.5f / fy;

    // ---- all 2048 keys (only tz + validity needed) ----
    for (int i = t; i < NGAUSS; i += 256) {
        float mx = means[i*3+0], my = means[i*3+1], mz = means[i*3+2];
        float tzk = R20*mx + R21*my + R22*mz + Tz;
        float keyf = (tzk > NEARP) ? tzk : __int_as_float(0x7F800000);  // +inf
        sk[i] = (((unsigned long long)__float_as_uint(keyf)) << 32) | (unsigned)i;
    }
    if (t < 128) scnt[t] = 0;
    __syncthreads();

    // ---- full projection of my element (half-0 threads only) ----
    float4 a0, a1, cu;
    if (h == 0) {
        const int n = e;
        float qw = rots[n*4+0], qx = rots[n*4+1], qy = rots[n*4+2], qz = rots[n*4+3];
        float inv = rsqrtf(qw*qw + qx*qx + qy*qy + qz*qz);
        qw *= inv; qx *= inv; qy *= inv; qz *= inv;
        float r00 = 1.f - 2.f*(qy*qy + qz*qz), r01 = 2.f*(qx*qy - qw*qz), r02 = 2.f*(qx*qz + qw*qy);
        float r10 = 2.f*(qx*qy + qw*qz), r11 = 1.f - 2.f*(qx*qx + qz*qz), r12 = 2.f*(qy*qz - qw*qx);
        float r20 = 2.f*(qx*qz - qw*qy), r21 = 2.f*(qy*qz + qw*qx), r22 = 1.f - 2.f*(qx*qx + qy*qy);

        float sx = scales[n*3+0], sy = scales[n*3+1], sz = scales[n*3+2];
        float m00 = r00*sx, m01 = r01*sy, m02 = r02*sz;
        float m10 = r10*sx, m11 = r11*sy, m12 = r12*sz;
        float m20 = r20*sx, m21 = r21*sy, m22 = r22*sz;

        float S00 = m00*m00 + m01*m01 + m02*m02;
        float S01 = m00*m10 + m01*m11 + m02*m12;
        float S02 = m00*m20 + m01*m21 + m02*m22;
        float S11 = m10*m10 + m11*m11 + m12*m12;
        float S12 = m10*m20 + m11*m21 + m12*m22;
        float S22 = m20*m20 + m21*m21 + m22*m22;

        float mx = means[n*3+0], my = means[n*3+1], mz = means[n*3+2];
        float tx = R00*mx + R01*my + R02*mz + Tx;
        float ty = R10*mx + R11*my + R12*mz + Ty;
        float tz = R20*mx + R21*my + R22*mz + Tz;

        bool  valid = tz > NEARP;
        float tzs   = valid ? tz : 1.0f;
        float txtz  = fminf(fmaxf(tx/tzs, -1.3f*tanfovx), 1.3f*tanfovx);
        float tytz  = fminf(fmaxf(ty/tzs, -1.3f*tanfovy), 1.3f*tanfovy);

        float A00 = R00*S00 + R01*S01 + R02*S02;
        float A01 = R00*S01 + R01*S11 + R02*S12;
        float A02 = R00*S02 + R01*S12 + R02*S22;
        float A10 = R10*S00 + R11*S01 + R12*S02;
        float A11 = R10*S01 + R11*S11 + R12*S12;
        float A12 = R10*S02 + R11*S12 + R12*S22;
        float A20 = R20*S00 + R21*S01 + R22*S02;
        float A21 = R20*S01 + R21*S11 + R22*S12;
        float A22 = R20*S02 + R21*S12 + R22*S22;
        float C00 = A00*R00 + A01*R01 + A02*R02;
        float C01 = A00*R10 + A01*R11 + A02*R12;
        float C02 = A00*R20 + A01*R21 + A02*R22;
        float C11 = A10*R10 + A11*R11 + A12*R12;
        float C12 = A10*R20 + A11*R21 + A12*R22;
        float C22 = A20*R20 + A21*R21 + A22*R22;

        float j00 = fx / tzs, j02 = -fx * txtz / tzs;
        float j11 = fy / tzs, j12 = -fy * tytz / tzs;
        float u0 = j00*C00 + j02*C02;
        float u1 = j00*C01 + j02*C12;
        float u2 = j00*C02 + j02*C22;
        float w1 = j11*C11 + j12*C12;
        float w2 = j11*C12 + j12*C22;
        float cov00 = u0*j00 + u2*j02;
        float cov01 = u1*j11 + u2*j12;
        float cov11 = w1*j11 + w2*j12;

        float a = cov00 + DILATE, b = cov01, c = cov11 + DILATE;
        float det = a*c - b*b;
        if (det == 0.f) det = 1.f;
        float ca = c / det, cb = -b / det, cc = a / det;

        float px = fx * tx / tzs + ((float)IMW - cx) - 0.5f;
        float py = fy * ty / tzs + ((float)IMH - cy) - 0.5f;
        float op = valid ? opac[n] : 0.f;

        // bbox radii of alpha >= 1/255 level set; NaN radii (op<=1/255) -> culled
        float lt = __logf(255.f * op);
        float rx = sqrtf(2.f * lt * a) * 1.0001f + 1e-3f;
        float ry = sqrtf(2.f * lt * c) * 1.0001f + 1e-3f;

        a0 = make_float4(px, py, ca, cb);
        a1 = make_float4(cc, op, tz, __int_as_float(n));
        cu = make_float4(px, py, rx, ry);
    }

    // ---- rank: 2 threads per element, one key-half each (broadcast LDS) ----
    const unsigned long long ke = sk[e];
    int cnt = 0;
    const int base = h * (NGAUSS / 2);
#pragma unroll 16
    for (int s = 0; s < NGAUSS / 2; s++)
        cnt += (sk[base + s] < ke) ? 1 : 0;
    atomicAdd(&scnt[e_loc], cnt);
    __syncthreads();

    // ---- scatter directly from registers ----
    if (h == 0) {
        int r = scnt[e_loc];
        g_sorted[v][r][0] = a0;
        g_sorted[v][r][1] = a1;
        g_cull  [v][r]    = cu;
    }
}

// ---------------------------------------------------------------------------
// Phase 2: transmit — cull + compaction (persisted), per-pixel segment
// transmittance. Also zeroes the output chunkwise (blend atomics depend on it).
// ---------------------------------------------------------------------------
__global__ void __launch_bounds__(64) transmit(float* __restrict__ out, int out_count)
{
    const int vz   = blockIdx.z;
    const int v    = vz / NSEG, seg = vz % NSEG;
    const int tile = blockIdx.y * NTILEX + blockIdx.x;
    const int ix   = blockIdx.x * 8 + threadIdx.x;
    const int iy   = blockIdx.y * 8 + threadIdx.y;
    const int tid  = threadIdx.y * 8 + threadIdx.x;
    const int wid  = tid >> 5, lane = tid & 31;
    const float X = (float)ix, Y = (float)iy;
    const float xmin = (float)(blockIdx.x * 8), xmax = xmin + 7.0f;
    const float ymin = (float)(blockIdx.y * 8), ymax = ymin + 7.0f;
    const unsigned lmask = (1u << lane) - 1u;

    // ---- zero my chunk of the output ----
    {
        const int ngrid = NTILE * NVIEW * NSEG;
        const int chunk = (out_count + ngrid - 1) / ngrid;
        const int base  = (vz * NTILE + tile) * chunk;
        for (int i = tid; i < chunk; i += 64) {
            int o = base + i;
            if (o < out_count) out[o] = 0.f;
        }
    }

    __shared__ float4 s0[BATCH + 4], s1[BATCH + 4];
    __shared__ unsigned sball[8];

    // ---- cull the single 256-gaussian batch of this segment ----
    const int base = seg * SEGLEN;
    float4 cd[4];
#pragma unroll
    for (int k = 0; k < 4; k++) cd[k] = g_cull[v][base + k * 64 + tid];

    bool hit[4];
    unsigned myb[4];
#pragma unroll
    for (int k = 0; k < 4; k++) {
        // NaN-safe: any NaN -> false -> culled
        hit[k] = (cd[k].x - cd[k].z <= xmax) && (cd[k].x + cd[k].z >= xmin) &&
                 (cd[k].y - cd[k].w <= ymax) && (cd[k].y + cd[k].w >= ymin);
        myb[k] = __ballot_sync(0xffffffffu, hit[k]);
    }
    if (lane == 0) {
#pragma unroll
        for (int k = 0; k < 4; k++) sball[k * 2 + wid] = myb[k];
    }
    __syncthreads();

    unsigned bl[8];
    int total = 0;
#pragma unroll
    for (int i = 0; i < 8; i++) { bl[i] = sball[i]; total += __popc(bl[i]); }

#pragma unroll
    for (int k = 0; k < 4; k++) {
        if (hit[k]) {
            int ord = k * 2 + wid;
            int off = 0;
            for (int i = 0; i < ord; i++) off += __popc(bl[i]);
            off += __popc(myb[k] & lmask);
            int g = base + k * 64 + tid;
            s0[off] = g_sorted[v][g][0];
            s1[off] = g_sorted[v][g][1];
        }
    }
    // pad to multiple of 4 with inert dummies (op=0 -> alpha 0)
    int pad = (4 - (total & 3)) & 3;
    if (tid < pad) {
        s0[total + tid] = make_float4(0.f, 0.f, 0.f, 0.f);
        s1[total + tid] = make_float4(0.f, 0.f, 0.f, 0.f);
    }
    const int totalp = total + pad;
    __syncthreads();

    // ---- persist compacted list for blend ----
    for (int i = tid; i < totalp; i += 64) {
        g_list0[v][seg][tile][i] = s0[i];
        g_list1[v][seg][tile][i] = s1[i];
    }
    if (tid == 0) g_cnt[v][seg][tile] = totalp;

    // ---- per-pixel transmittance ----
    float T = 1.f;
    for (int j = 0; j < totalp; j += 4) {
#pragma unroll
        for (int u = 0; u < 4; u++) {
            float4 A = s0[j + u];
            float4 B = s1[j + u];
            float dx = X - A.x, dy = Y - A.y;
            float power = -0.5f * (A.z * dx * dx + B.x * dy * dy) - A.w * dx * dy;
            float al = fminf(0.99f, B.y * __expf(power));
            bool skip = (power > 0.f) || !(al >= ALPHA_MIN);
            T *= skip ? 1.f : (1.f - al);
        }
        // safe early out: recorded T >= true T but <= 1e-8 << T_EPS, so any
        // downstream prefix containing this factor still fails the gate.
        if (__all_sync(0xffffffffu, T < 1e-8f)) break;
    }
    g_T[v][seg][iy * IMW + ix] = T;
}

// ---------------------------------------------------------------------------
// Phase 3: blend — gated color accumulation from the precompacted list.
// Channel-split: grid z = (v*NSEG+seg)*2 + half; each CTA does 16 channels.
// ---------------------------------------------------------------------------
__global__ void __launch_bounds__(64) blend(const float* __restrict__ colors,
                                            float* __restrict__ out)
{
    const int vzh  = blockIdx.z;
    const int half = vzh & 1;
    const int vz   = vzh >> 1;
    const int v    = vz / NSEG, seg = vz % NSEG;
    const int tile = blockIdx.y * NTILEX + blockIdx.x;
    const int ix   = blockIdx.x * 8 + threadIdx.x;
    const int iy   = blockIdx.y * 8 + threadIdx.y;
    const int tid  = threadIdx.y * 8 + threadIdx.x;
    const int pix  = iy * IMW + ix;
    const float X = (float)ix, Y = (float)iy;

    float T = 1.f;
#pragma unroll
    for (int s = 0; s < NSEG - 1; s++)
        if (s < seg) T *= g_T[v][s][pix];

    // whole-CTA skip: every weight in this segment would be gated to 0
    if (__syncthreads_and(T < T_EPS)) return;

    const int cnt = g_cnt[v][seg][tile];

    __shared__ float4 s0[SEGLEN + 4], s1[SEGLEN + 4];
    for (int i = tid; i < cnt; i += 64) {
        s0[i] = g_list0[v][seg][tile][i];
        s1[i] = g_list1[v][seg][tile][i];
    }
    __syncthreads();

    float acc[16];
#pragma unroll
    for (int c = 0; c < 16; c++) acc[c] = 0.f;
    float dacc = 0.f;
    bool applied = false;

    for (int j = 0; j < cnt; j += 4) {
        float w4[4], tz4[4];
        int   id4[4];
#pragma unroll
        for (int u = 0; u < 4; u++) {
            float4 A = s0[j + u];
            float4 B = s1[j + u];
            float dx = X - A.x, dy = Y - A.y;
            float power = -0.5f * (A.z * dx * dx + B.x * dy * dy) - A.w * dx * dy;
            float al = fminf(0.99f, B.y * __expf(power));
            bool skip = (power > 0.f) || !(al >= ALPHA_MIN);
            float ale = skip ? 0.f : al;
            float Tn  = T * (1.f - ale);
            w4[u]  = (Tn >= T_EPS) ? ale * T : 0.f;
            tz4[u] = B.z;
            id4[u] = __float_as_int(B.w);
            T = Tn;
        }
#pragma unroll
        for (int u = 0; u < 4; u++) {
            if (w4[u] != 0.f) {
                applied = true;
                float w = w4[u];
                const float4* crow = (const float4*)
                    (colors + (size_t)((unsigned)id4[u]) * NCH + half * 16);
#pragma unroll
                for (int c4 = 0; c4 < 4; c4++) {
                    float4 cv = crow[c4];
                    acc[c4*4+0] += w * cv.x;
                    acc[c4*4+1] += w * cv.y;
                    acc[c4*4+2] += w * cv.z;
                    acc[c4*4+3] += w * cv.w;
                }
                dacc += w * tz4[u];
            }
        }
        if (__all_sync(0xffffffffu, T < T_EPS)) break;   // per-warp; no smem reuse
    }

    if (applied) {
#pragma unroll
        for (int c = 0; c < 16; c++)
            atomicAdd(&out[(size_t)(v * NCH + half * 16 + c) * NPIX + pix], acc[c]);
        if (half == 0)
            atomicAdd(&out[(size_t)NVIEW * NCH * NPIX + (size_t)v * NPIX + pix], dacc);
    }
}

// ---------------------------------------------------------------------------
extern "C" void kernel_launch(void* const* d_in, const int* in_sizes, int n_in,
                              void* d_out, int out_size)
{
    const float* means   = (const float*)d_in[0];
    const float* colors  = (const float*)d_in[1];
    const float* opac    = (const float*)d_in[2];
    const float* scales  = (const float*)d_in[3];
    const float* rots    = (const float*)d_in[4];
    const float* cam2img = (const float*)d_in[5];
    const float* cam2ego = (const float*)d_in[6];
    float* out = (float*)d_out;

    prep    <<<dim3(NVIEW, NGAUSS / 128), 256>>>(means, opac, scales, rots, cam2img, cam2ego);
    transmit<<<dim3(NTILEX, NTILEY, NVIEW * NSEG), dim3(8, 8)>>>(out, out_size);
    blend   <<<dim3(NTILEX, NTILEY, NVIEW * NSEG * 2), dim3(8, 8)>>>(colors, out);
}

// round 15
// speedup vs baseline: 2.6119x; 1.3021x over previous
#include <cuda_runtime.h>

#define NGAUSS 2048
#define NCH    32
#define IMH    80
#define IMW    144
#define NPIX   (IMH*IMW)
#define NTILEX (IMW/8)
#define NTILEY (IMH/8)
#define NTILE  (NTILEX*NTILEY)
#define NVIEW  2
#define NSEG   8
#define SEGLEN (NGAUSS/NSEG)
#define NEARP  0.2f
#define DILATE 0.3f
#define ALPHA_MIN (1.0f/255.0f)
#define T_EPS  1e-4f
#define BATCH  256   // == SEGLEN: one cull round per segment

// prep decomposition
#define EPC    32                 // elements ranked per CTA
#define PWARPS 16                 // warps per prep CTA (512 threads)
#define KRANGE (NGAUSS/PWARPS)    // 128 keys counted per warp

// depth-sorted per-gaussian attrs: [0]={px,py,ca,cb} [1]={cc,op,tz,idx} ; cull={px,py,rx,ry}
__device__ float4 g_sorted[NVIEW][NGAUSS][2];
__device__ float4 g_cull  [NVIEW][NGAUSS];
// segmented compositing scratch
__device__ float  g_T    [NVIEW][NSEG][NPIX];
__device__ float4 g_list0[NVIEW][NSEG][NTILE][SEGLEN];
__device__ float4 g_list1[NVIEW][NSEG][NTILE][SEGLEN];
__device__ int    g_cnt  [NVIEW][NSEG][NTILE];

// ---------------------------------------------------------------------------
// Phase 1: fused projection + enumeration(rank) sort + scatter.
// grid (NVIEW, NGAUSS/EPC) x 512. Each CTA:
//   - computes ALL 2048 sort keys locally into smem (tz needs one rotation row),
//   - warp w counts keys in range [w*128, (w+1)*128) for ALL 32 elements
//     (lane l owns element l; broadcast smem reads, conflict-free),
//   - threads t<32 fully project their element (registers) and scatter by rank.
// Keys are unique 64-bit (tz_bits<<32)|idx, so rank = #{key_j < key_e} is a
// stable ascending permutation == jnp.argsort. No inter-CTA dependencies.
// ---------------------------------------------------------------------------
__global__ void __launch_bounds__(512) prep(const float* __restrict__ means,
                                            const float* __restrict__ opac,
                                            const float* __restrict__ scales,
                                            const float* __restrict__ rots,
                                            const float* __restrict__ cam2img,
                                            const float* __restrict__ cam2ego)
{
    const int v    = blockIdx.x;
    const int t    = threadIdx.x;
    const int w    = t >> 5;      // warp id: key range
    const int lane = t & 31;      // element within CTA
    const int ebase = blockIdx.y * EPC;

    __shared__ unsigned long long sk[NGAUSS];
    __shared__ int scnt[EPC];

    const float* Km = cam2img + v * 9;
    const float* E  = cam2ego + v * 16;
    const float fx = Km[0], fy = Km[4], cx = Km[2], cy = Km[5];

    const float R00 = E[0], R01 = E[4], R02 = E[8];
    const float R10 = E[1], R11 = E[5], R12 = E[9];
    const float R20 = E[2], R21 = E[6], R22 = E[10];
    const float ex = E[3], ey = E[7], ez = E[11];
    const float Tx = -(R00*ex + R01*ey + R02*ez);
    const float Ty = -(R10*ex + R11*ey + R12*ez);
    const float Tz = -(R20*ex + R21*ey + R22*ez);
    const float tanfovx = (float)IMW * 0.5f / fx;
    const float tanfovy = (float)IMH * 0.5f / fy;

    // ---- all 2048 keys (only tz + validity needed) ----
    for (int i = t; i < NGAUSS; i += 512) {
        float mx = means[i*3+0], my = means[i*3+1], mz = means[i*3+2];
        float tzk = R20*mx + R21*my + R22*mz + Tz;
        float keyf = (tzk > NEARP) ? tzk : __int_as_float(0x7F800000);  // +inf
        sk[i] = (((unsigned long long)__float_as_uint(keyf)) << 32) | (unsigned)i;
    }
    if (t < EPC) scnt[t] = 0;
    __syncthreads();

    // ---- full projection of my element (threads t < EPC only) ----
    float4 a0, a1, cu;
    if (t < EPC) {
        const int n = ebase + t;
        float qw = rots[n*4+0], qx = rots[n*4+1], qy = rots[n*4+2], qz = rots[n*4+3];
        float inv = rsqrtf(qw*qw + qx*qx + qy*qy + qz*qz);
        qw *= inv; qx *= inv; qy *= inv; qz *= inv;
        float r00 = 1.f - 2.f*(qy*qy + qz*qz), r01 = 2.f*(qx*qy - qw*qz), r02 = 2.f*(qx*qz + qw*qy);
        float r10 = 2.f*(qx*qy + qw*qz), r11 = 1.f - 2.f*(qx*qx + qz*qz), r12 = 2.f*(qy*qz - qw*qx);
        float r20 = 2.f*(qx*qz - qw*qy), r21 = 2.f*(qy*qz + qw*qx), r22 = 1.f - 2.f*(qx*qx + qy*qy);

        float sx = scales[n*3+0], sy = scales[n*3+1], sz = scales[n*3+2];
        float m00 = r00*sx, m01 = r01*sy, m02 = r02*sz;
        float m10 = r10*sx, m11 = r11*sy, m12 = r12*sz;
        float m20 = r20*sx, m21 = r21*sy, m22 = r22*sz;

        float S00 = m00*m00 + m01*m01 + m02*m02;
        float S01 = m00*m10 + m01*m11 + m02*m12;
        float S02 = m00*m20 + m01*m21 + m02*m22;
        float S11 = m10*m10 + m11*m11 + m12*m12;
        float S12 = m10*m20 + m11*m21 + m12*m22;
        float S22 = m20*m20 + m21*m21 + m22*m22;

        float mx = means[n*3+0], my = means[n*3+1], mz = means[n*3+2];
        float tx = R00*mx + R01*my + R02*mz + Tx;
        float ty = R10*mx + R11*my + R12*mz + Ty;
        float tz = R20*mx + R21*my + R22*mz + Tz;

        bool  valid = tz > NEARP;
        float tzs   = valid ? tz : 1.0f;
        float txtz  = fminf(fmaxf(tx/tzs, -1.3f*tanfovx), 1.3f*tanfovx);
        float tytz  = fminf(fmaxf(ty/tzs, -1.3f*tanfovy), 1.3f*tanfovy);

        float A00 = R00*S00 + R01*S01 + R02*S02;
        float A01 = R00*S01 + R01*S11 + R02*S12;
        float A02 = R00*S02 + R01*S12 + R02*S22;
        float A10 = R10*S00 + R11*S01 + R12*S02;
        float A11 = R10*S01 + R11*S11 + R12*S12;
        float A12 = R10*S02 + R11*S12 + R12*S22;
        float A20 = R20*S00 + R21*S01 + R22*S02;
        float A21 = R20*S01 + R21*S11 + R22*S12;
        float A22 = R20*S02 + R21*S12 + R22*S22;
        float C00 = A00*R00 + A01*R01 + A02*R02;
        float C01 = A00*R10 + A01*R11 + A02*R12;
        float C02 = A00*R20 + A01*R21 + A02*R22;
        float C11 = A10*R10 + A11*R11 + A12*R12;
        float C12 = A10*R20 + A11*R21 + A12*R22;
        float C22 = A20*R20 + A21*R21 + A22*R22;

        float j00 = fx / tzs, j02 = -fx * txtz / tzs;
        float j11 = fy / tzs, j12 = -fy * tytz / tzs;
        float u0 = j00*C00 + j02*C02;
        float u1 = j00*C01 + j02*C12;
        float u2 = j00*C02 + j02*C22;
        float w1 = j11*C11 + j12*C12;
        float w2 = j11*C12 + j12*C22;
        float cov00 = u0*j00 + u2*j02;
        float cov01 = u1*j11 + u2*j12;
        float cov11 = w1*j11 + w2*j12;

        float a = cov00 + DILATE, b = cov01, c = cov11 + DILATE;
        float det = a*c - b*b;
        if (det == 0.f) det = 1.f;
        float ca = c / det, cb = -b / det, cc = a / det;

        float px = fx * tx / tzs + ((float)IMW - cx) - 0.5f;
        float py = fy * ty / tzs + ((float)IMH - cy) - 0.5f;
        float op = valid ? opac[n] : 0.f;

        // bbox radii of alpha >= 1/255 level set; NaN radii (op<=1/255) -> culled
        float lt = __logf(255.f * op);
        float rx = sqrtf(2.f * lt * a) * 1.0001f + 1e-3f;
        float ry = sqrtf(2.f * lt * c) * 1.0001f + 1e-3f;

        a0 = make_float4(px, py, ca, cb);
        a1 = make_float4(cc, op, tz, __int_as_float(n));
        cu = make_float4(px, py, rx, ry);
    }

    // ---- rank: warp w counts its 128-key range for element 'lane' ----
    const unsigned long long ke = sk[ebase + lane];
    int cnt = 0;
    const int kbase = w * KRANGE;
#pragma unroll 16
    for (int s = 0; s < KRANGE; s++)
        cnt += (sk[kbase + s] < ke) ? 1 : 0;
    atomicAdd(&scnt[lane], cnt);     // 32 distinct addrs per warp: conflict-free
    __syncthreads();

    // ---- scatter directly from registers ----
    if (t < EPC) {
        int r = scnt[t];
        g_sorted[v][r][0] = a0;
        g_sorted[v][r][1] = a1;
        g_cull  [v][r]    = cu;
    }
}

// ---------------------------------------------------------------------------
// Phase 2: transmit — cull + compaction (persisted), per-pixel segment
// transmittance. Also zeroes the output chunkwise (blend atomics depend on it).
// ---------------------------------------------------------------------------
__global__ void __launch_bounds__(64) transmit(float* __restrict__ out, int out_count)
{
    const int vz   = blockIdx.z;
    const int v    = vz / NSEG, seg = vz % NSEG;
    const int tile = blockIdx.y * NTILEX + blockIdx.x;
    const int ix   = blockIdx.x * 8 + threadIdx.x;
    const int iy   = blockIdx.y * 8 + threadIdx.y;
    const int tid  = threadIdx.y * 8 + threadIdx.x;
    const int wid  = tid >> 5, lane = tid & 31;
    const float X = (float)ix, Y = (float)iy;
    const float xmin = (float)(blockIdx.x * 8), xmax = xmin + 7.0f;
    const float ymin = (float)(blockIdx.y * 8), ymax = ymin + 7.0f;
    const unsigned lmask = (1u << lane) - 1u;

    // ---- zero my chunk of the output ----
    {
        const int ngrid = NTILE * NVIEW * NSEG;
        const int chunk = (out_count + ngrid - 1) / ngrid;
        const int base  = (vz * NTILE + tile) * chunk;
        for (int i = tid; i < chunk; i += 64) {
            int o = base + i;
            if (o < out_count) out[o] = 0.f;
        }
    }

    __shared__ float4 s0[BATCH + 4], s1[BATCH + 4];
    __shared__ unsigned sball[8];

    // ---- cull the single 256-gaussian batch of this segment ----
    const int base = seg * SEGLEN;
    float4 cd[4];
#pragma unroll
    for (int k = 0; k < 4; k++) cd[k] = g_cull[v][base + k * 64 + tid];

    bool hit[4];
    unsigned myb[4];
#pragma unroll
    for (int k = 0; k < 4; k++) {
        // NaN-safe: any NaN -> false -> culled
        hit[k] = (cd[k].x - cd[k].z <= xmax) && (cd[k].x + cd[k].z >= xmin) &&
                 (cd[k].y - cd[k].w <= ymax) && (cd[k].y + cd[k].w >= ymin);
        myb[k] = __ballot_sync(0xffffffffu, hit[k]);
    }
    if (lane == 0) {
#pragma unroll
        for (int k = 0; k < 4; k++) sball[k * 2 + wid] = myb[k];
    }
    __syncthreads();

    unsigned bl[8];
    int total = 0;
#pragma unroll
    for (int i = 0; i < 8; i++) { bl[i] = sball[i]; total += __popc(bl[i]); }

#pragma unroll
    for (int k = 0; k < 4; k++) {
        if (hit[k]) {
            int ord = k * 2 + wid;
            int off = 0;
            for (int i = 0; i < ord; i++) off += __popc(bl[i]);
            off += __popc(myb[k] & lmask);
            int g = base + k * 64 + tid;
            s0[off] = g_sorted[v][g][0];
            s1[off] = g_sorted[v][g][1];
        }
    }
    // pad to multiple of 4 with inert dummies (op=0 -> alpha 0)
    int pad = (4 - (total & 3)) & 3;
    if (tid < pad) {
        s0[total + tid] = make_float4(0.f, 0.f, 0.f, 0.f);
        s1[total + tid] = make_float4(0.f, 0.f, 0.f, 0.f);
    }
    const int totalp = total + pad;
    __syncthreads();

    // ---- persist compacted list for blend ----
    for (int i = tid; i < totalp; i += 64) {
        g_list0[v][seg][tile][i] = s0[i];
        g_list1[v][seg][tile][i] = s1[i];
    }
    if (tid == 0) g_cnt[v][seg][tile] = totalp;

    // ---- per-pixel transmittance ----
    float T = 1.f;
    for (int j = 0; j < totalp; j += 4) {
#pragma unroll
        for (int u = 0; u < 4; u++) {
            float4 A = s0[j + u];
            float4 B = s1[j + u];
            float dx = X - A.x, dy = Y - A.y;
            float power = -0.5f * (A.z * dx * dx + B.x * dy * dy) - A.w * dx * dy;
            float al = fminf(0.99f, B.y * __expf(power));
            bool skip = (power > 0.f) || !(al >= ALPHA_MIN);
            T *= skip ? 1.f : (1.f - al);
        }
        // safe early out: recorded T >= true T but <= 1e-8 << T_EPS, so any
        // downstream prefix containing this factor still fails the gate.
        if (__all_sync(0xffffffffu, T < 1e-8f)) break;
    }
    g_T[v][seg][iy * IMW + ix] = T;
}

// ---------------------------------------------------------------------------
// Phase 3: blend — gated color accumulation from the precompacted list.
// Channel-split: grid z = (v*NSEG+seg)*2 + half; each CTA does 16 channels.
// ---------------------------------------------------------------------------
__global__ void __launch_bounds__(64) blend(const float* __restrict__ colors,
                                            float* __restrict__ out)
{
    const int vzh  = blockIdx.z;
    const int half = vzh & 1;
    const int vz   = vzh >> 1;
    const int v    = vz / NSEG, seg = vz % NSEG;
    const int tile = blockIdx.y * NTILEX + blockIdx.x;
    const int ix   = blockIdx.x * 8 + threadIdx.x;
    const int iy   = blockIdx.y * 8 + threadIdx.y;
    const int tid  = threadIdx.y * 8 + threadIdx.x;
    const int pix  = iy * IMW + ix;
    const float X = (float)ix, Y = (float)iy;

    float T = 1.f;
#pragma unroll
    for (int s = 0; s < NSEG - 1; s++)
        if (s < seg) T *= g_T[v][s][pix];

    // whole-CTA skip: every weight in this segment would be gated to 0
    if (__syncthreads_and(T < T_EPS)) return;

    const int cnt = g_cnt[v][seg][tile];

    __shared__ float4 s0[SEGLEN + 4], s1[SEGLEN + 4];
    for (int i = tid; i < cnt; i += 64) {
        s0[i] = g_list0[v][seg][tile][i];
        s1[i] = g_list1[v][seg][tile][i];
    }
    __syncthreads();

    float acc[16];
#pragma unroll
    for (int c = 0; c < 16; c++) acc[c] = 0.f;
    float dacc = 0.f;
    bool applied = false;

    for (int j = 0; j < cnt; j += 4) {
        float w4[4], tz4[4];
        int   id4[4];
#pragma unroll
        for (int u = 0; u < 4; u++) {
            float4 A = s0[j + u];
            float4 B = s1[j + u];
            float dx = X - A.x, dy = Y - A.y;
            float power = -0.5f * (A.z * dx * dx + B.x * dy * dy) - A.w * dx * dy;
            float al = fminf(0.99f, B.y * __expf(power));
            bool skip = (power > 0.f) || !(al >= ALPHA_MIN);
            float ale = skip ? 0.f : al;
            float Tn  = T * (1.f - ale);
            w4[u]  = (Tn >= T_EPS) ? ale * T : 0.f;
            tz4[u] = B.z;
            id4[u] = __float_as_int(B.w);
            T = Tn;
        }
#pragma unroll
        for (int u = 0; u < 4; u++) {
            if (w4[u] != 0.f) {
                applied = true;
                float w = w4[u];
                const float4* crow = (const float4*)
                    (colors + (size_t)((unsigned)id4[u]) * NCH + half * 16);
#pragma unroll
                for (int c4 = 0; c4 < 4; c4++) {
                    float4 cv = crow[c4];
                    acc[c4*4+0] += w * cv.x;
                    acc[c4*4+1] += w * cv.y;
                    acc[c4*4+2] += w * cv.z;
                    acc[c4*4+3] += w * cv.w;
                }
                dacc += w * tz4[u];
            }
        }
        if (__all_sync(0xffffffffu, T < T_EPS)) break;   // per-warp; no smem reuse
    }

    if (applied) {
#pragma unroll
        for (int c = 0; c < 16; c++)
            atomicAdd(&out[(size_t)(v * NCH + half * 16 + c) * NPIX + pix], acc[c]);
        if (half == 0)
            atomicAdd(&out[(size_t)NVIEW * NCH * NPIX + (size_t)v * NPIX + pix], dacc);
    }
}

// ---------------------------------------------------------------------------
extern "C" void kernel_launch(void* const* d_in, const int* in_sizes, int n_in,
                              void* d_out, int out_size)
{
    const float* means   = (const float*)d_in[0];
    const float* colors  = (const float*)d_in[1];
    const float* opac    = (const float*)d_in[2];
    const float* scales  = (const float*)d_in[3];
    const float* rots    = (const float*)d_in[4];
    const float* cam2img = (const float*)d_in[5];
    const float* cam2ego = (const float*)d_in[6];
    float* out = (float*)d_out;

    prep    <<<dim3(NVIEW, NGAUSS / EPC), 512>>>(means, opac, scales, rots, cam2img, cam2ego);
    transmit<<<dim3(NTILEX, NTILEY, NVIEW * NSEG), dim3(8, 8)>>>(out, out_size);
    blend   <<<dim3(NTILEX, NTILEY, NVIEW * NSEG * 2), dim3(8, 8)>>>(colors, out);
}